// round 1
// baseline (speedup 1.0000x reference)
#include <cuda_runtime.h>
#include <math.h>

#define Bsz 4
#define Ssz 2048
#define Csz 1024
#define Hn  16
#define Dh  64
#define Msz (Bsz*Ssz)   // 8192

// Scratch (allocation-free): 3x32MB + 3x32MB + 32MB
__device__ float g_a[3][(size_t)Msz*Csz];
__device__ float g_b[3][(size_t)Msz*Csz];
__device__ float g_att[(size_t)Msz*Csz];

// ---------------------------------------------------------------------------
// SGEMM: C[M,N] = act(A[M,K] @ B + bias).  TRANSB: B is [N,K] (row-major),
// else B is [K,N]. BM=BN=128, BK=8, 256 threads, 8x8 micro-tile.
// ---------------------------------------------------------------------------
template<bool TRANSB, bool SILU>
__global__ __launch_bounds__(256) void sgemm_k(
    const float* __restrict__ A, const float* __restrict__ Bm,
    const float* __restrict__ bias, float* __restrict__ C,
    int M, int N, int K)
{
    __shared__ float As[8][128];
    __shared__ float Bs[8][128];

    const int tid = threadIdx.x;
    const int m0 = blockIdx.y * 128;
    const int n0 = blockIdx.x * 128;
    const int tr = tid >> 4;       // 0..15
    const int tc = tid & 15;       // 0..15

    float acc[8][8];
#pragma unroll
    for (int i = 0; i < 8; i++)
#pragma unroll
        for (int j = 0; j < 8; j++) acc[i][j] = 0.f;

    const int arow = tid >> 1;           // 0..127
    const int ak   = (tid & 1) * 4;      // 0 or 4
    const float* Aptr = A + (size_t)(m0 + arow) * K + ak;

    for (int k0 = 0; k0 < K; k0 += 8) {
        float4 av = *(const float4*)(Aptr + k0);
        As[ak+0][arow] = av.x; As[ak+1][arow] = av.y;
        As[ak+2][arow] = av.z; As[ak+3][arow] = av.w;

        if (TRANSB) {
            const int bn = tid >> 1, bk = (tid & 1) * 4;
            float4 bv = *(const float4*)(Bm + (size_t)(n0 + bn) * K + k0 + bk);
            Bs[bk+0][bn] = bv.x; Bs[bk+1][bn] = bv.y;
            Bs[bk+2][bn] = bv.z; Bs[bk+3][bn] = bv.w;
        } else {
            const int bk = tid >> 5, bn4 = (tid & 31) * 4;
            float4 bv = *(const float4*)(Bm + (size_t)(k0 + bk) * N + n0 + bn4);
            *(float4*)&Bs[bk][bn4] = bv;
        }
        __syncthreads();

#pragma unroll
        for (int kk = 0; kk < 8; kk++) {
            float a[8], b[8];
            *(float4*)&a[0] = *(const float4*)&As[kk][tr*8];
            *(float4*)&a[4] = *(const float4*)&As[kk][tr*8+4];
            *(float4*)&b[0] = *(const float4*)&Bs[kk][tc*8];
            *(float4*)&b[4] = *(const float4*)&Bs[kk][tc*8+4];
#pragma unroll
            for (int i = 0; i < 8; i++)
#pragma unroll
                for (int j = 0; j < 8; j++)
                    acc[i][j] += a[i] * b[j];
        }
        __syncthreads();
    }

#pragma unroll
    for (int i = 0; i < 8; i++) {
        const int row = m0 + tr*8 + i;
#pragma unroll
        for (int j = 0; j < 8; j += 4) {
            float4 o;
            float* oo = &o.x;
#pragma unroll
            for (int t = 0; t < 4; t++) {
                const int col = n0 + tc*8 + j + t;
                float v = acc[i][j+t] + bias[col];
                if (SILU) v = v / (1.f + __expf(-v));
                oo[t] = v;
            }
            *(float4*)(C + (size_t)row * N + n0 + tc*8 + j) = o;
        }
    }
}

// ---------------------------------------------------------------------------
// Depthwise conv k=3, pad=1 over sequence. in/out: [B,S,C]. dw: [C,1,3].
// ---------------------------------------------------------------------------
__global__ void dwconv_k(const float* __restrict__ in, const float* __restrict__ dw,
                         const float* __restrict__ dwb, float* __restrict__ out)
{
    const int idx = blockIdx.x * blockDim.x + threadIdx.x;   // over M*C/4
    const int c4 = (idx & (Csz/4 - 1)) * 4;
    const int m  = idx >> 8;                                  // / (Csz/4)
    const int s  = m & (Ssz - 1);

    float4 x0 = make_float4(0,0,0,0), x2 = make_float4(0,0,0,0);
    if (s > 0)        x0 = *(const float4*)(in + (size_t)(m-1)*Csz + c4);
    const float4 x1 =      *(const float4*)(in + (size_t)m*Csz + c4);
    if (s < Ssz - 1)  x2 = *(const float4*)(in + (size_t)(m+1)*Csz + c4);

    float4 o;
    const float* p0 = &x0.x; const float* p1 = &x1.x; const float* p2 = &x2.x;
    float* po = &o.x;
#pragma unroll
    for (int t = 0; t < 4; t++) {
        const int c = c4 + t;
        po[t] = dwb[c] + dw[c*3+0]*p0[t] + dw[c*3+1]*p1[t] + dw[c*3+2]*p2[t];
    }
    *(float4*)(out + (size_t)m*Csz + c4) = o;
}

// ---------------------------------------------------------------------------
// Row-wise L2 normalize over C=1024. One block per row, 256 threads.
// ---------------------------------------------------------------------------
__global__ void l2norm_k(float* __restrict__ buf)
{
    __shared__ float red[8];
    float* p = buf + (size_t)blockIdx.x * Csz;
    float4 v = *(float4*)(p + threadIdx.x*4);
    float ss = v.x*v.x + v.y*v.y + v.z*v.z + v.w*v.w;
#pragma unroll
    for (int off = 16; off; off >>= 1) ss += __shfl_xor_sync(0xffffffffu, ss, off);
    if ((threadIdx.x & 31) == 0) red[threadIdx.x >> 5] = ss;
    __syncthreads();
    if (threadIdx.x == 0) {
        float t = 0.f;
#pragma unroll
        for (int i = 0; i < 8; i++) t += red[i];
        red[0] = t;
    }
    __syncthreads();
    const float inv = 1.0f / fmaxf(sqrtf(red[0]), 1e-12f);
    v.x *= inv; v.y *= inv; v.z *= inv; v.w *= inv;
    *(float4*)(p + threadIdx.x*4) = v;
}

// ---------------------------------------------------------------------------
// Flash attention (fp32). Block = (b, h, 64-query tile), 256 threads.
// Thread (ty,tx)=(tid/16, tid%16) owns 4 q-rows x 4 cols. Online softmax with
// shfl_xor reductions within the 16-lane tx-group.
// ---------------------------------------------------------------------------
__global__ __launch_bounds__(256) void attn_k(
    const float* __restrict__ qg, const float* __restrict__ kg,
    const float* __restrict__ vg, const int* __restrict__ mask,
    float* __restrict__ og)
{
    extern __shared__ float sm[];
    float* Qs = sm;               // [64 d][64 i]
    float* Ks = sm + 4096;        // [64 d][64 j]
    float* Vs = sm + 8192;        // [64 j][64 d]
    float* Ps = sm + 12288;       // [64 j][65 i] (padded)
    int*   Ms = (int*)(sm + 12288 + 64*65);

    const int tid = threadIdx.x;
    const int q0  = blockIdx.x * 64;
    const int b   = blockIdx.y >> 4;
    const int h   = blockIdx.y & 15;
    const size_t base_bh = ((size_t)b * Ssz) * Csz + h * Dh;

    // Load Q tile, transposed to [d][i]
    const float* qq = qg + base_bh + (size_t)q0 * Csz;
#pragma unroll
    for (int r = 0; r < 4; r++) {
        const int f = tid + r*256;
        const int i = f >> 4, d4 = (f & 15) * 4;
        float4 v = *(const float4*)(qq + (size_t)i * Csz + d4);
        Qs[(d4+0)*64+i] = v.x; Qs[(d4+1)*64+i] = v.y;
        Qs[(d4+2)*64+i] = v.z; Qs[(d4+3)*64+i] = v.w;
    }

    const int ty = tid >> 4, tx = tid & 15;
    float m_r[4], l_r[4], acc[4][4];
#pragma unroll
    for (int i = 0; i < 4; i++) {
        m_r[i] = -1e30f; l_r[i] = 0.f;
#pragma unroll
        for (int j = 0; j < 4; j++) acc[i][j] = 0.f;
    }

    for (int k0 = 0; k0 < Ssz; k0 += 64) {
        __syncthreads();   // prior-iteration consumers of Ks/Vs/Ps done
        const float* kk_ = kg + base_bh + (size_t)k0 * Csz;
        const float* vv_ = vg + base_bh + (size_t)k0 * Csz;
#pragma unroll
        for (int r = 0; r < 4; r++) {
            const int f = tid + r*256;
            const int i = f >> 4, d4 = (f & 15) * 4;
            float4 kv = *(const float4*)(kk_ + (size_t)i * Csz + d4);
            Ks[(d4+0)*64+i] = kv.x; Ks[(d4+1)*64+i] = kv.y;
            Ks[(d4+2)*64+i] = kv.z; Ks[(d4+3)*64+i] = kv.w;
            float4 vv = *(const float4*)(vv_ + (size_t)i * Csz + d4);
            *(float4*)&Vs[i*64 + d4] = vv;
        }
        if (tid < 64) Ms[tid] = mask[(size_t)b * Ssz + k0 + tid];
        __syncthreads();

        // S = Q K^T (4x4 micro-tile per thread)
        float s[4][4];
#pragma unroll
        for (int i = 0; i < 4; i++)
#pragma unroll
            for (int j = 0; j < 4; j++) s[i][j] = 0.f;
#pragma unroll 16
        for (int d = 0; d < 64; d++) {
            const float a0 = Qs[d*64 + ty*4 + 0];
            const float a1 = Qs[d*64 + ty*4 + 1];
            const float a2 = Qs[d*64 + ty*4 + 2];
            const float a3 = Qs[d*64 + ty*4 + 3];
            const float4 bb = *(const float4*)&Ks[d*64 + tx*4];
            s[0][0]+=a0*bb.x; s[0][1]+=a0*bb.y; s[0][2]+=a0*bb.z; s[0][3]+=a0*bb.w;
            s[1][0]+=a1*bb.x; s[1][1]+=a1*bb.y; s[1][2]+=a1*bb.z; s[1][3]+=a1*bb.w;
            s[2][0]+=a2*bb.x; s[2][1]+=a2*bb.y; s[2][2]+=a2*bb.z; s[2][3]+=a2*bb.w;
            s[3][0]+=a3*bb.x; s[3][1]+=a3*bb.y; s[3][2]+=a3*bb.z; s[3][3]+=a3*bb.w;
        }
#pragma unroll
        for (int j = 0; j < 4; j++) {
            const bool mk = (Ms[tx*4 + j] != 0);
#pragma unroll
            for (int i = 0; i < 4; i++)
                s[i][j] = mk ? s[i][j] * 0.125f : -1e30f;
        }

        // Online softmax per q-row (state replicated across the 16 tx lanes)
#pragma unroll
        for (int i = 0; i < 4; i++) {
            float rm = fmaxf(fmaxf(s[i][0], s[i][1]), fmaxf(s[i][2], s[i][3]));
            rm = fmaxf(rm, __shfl_xor_sync(0xffffffffu, rm, 1));
            rm = fmaxf(rm, __shfl_xor_sync(0xffffffffu, rm, 2));
            rm = fmaxf(rm, __shfl_xor_sync(0xffffffffu, rm, 4));
            rm = fmaxf(rm, __shfl_xor_sync(0xffffffffu, rm, 8));
            const float mnew = fmaxf(m_r[i], rm);
            const float corr = __expf(m_r[i] - mnew);
            float rs = 0.f;
#pragma unroll
            for (int j = 0; j < 4; j++) {
                const float p = __expf(s[i][j] - mnew);
                s[i][j] = p;
                rs += p;
            }
            rs += __shfl_xor_sync(0xffffffffu, rs, 1);
            rs += __shfl_xor_sync(0xffffffffu, rs, 2);
            rs += __shfl_xor_sync(0xffffffffu, rs, 4);
            rs += __shfl_xor_sync(0xffffffffu, rs, 8);
            l_r[i] = l_r[i] * corr + rs;
            m_r[i] = mnew;
#pragma unroll
            for (int j = 0; j < 4; j++) acc[i][j] *= corr;
#pragma unroll
            for (int j = 0; j < 4; j++)
                Ps[(tx*4 + j)*65 + ty*4 + i] = s[i][j];
        }
        __syncthreads();

        // O += P V (P in smem transposed [j][i], V [j][d])
#pragma unroll 16
        for (int j = 0; j < 64; j++) {
            const float a0 = Ps[j*65 + ty*4 + 0];
            const float a1 = Ps[j*65 + ty*4 + 1];
            const float a2 = Ps[j*65 + ty*4 + 2];
            const float a3 = Ps[j*65 + ty*4 + 3];
            const float4 bb = *(const float4*)&Vs[j*64 + tx*4];
            acc[0][0]+=a0*bb.x; acc[0][1]+=a0*bb.y; acc[0][2]+=a0*bb.z; acc[0][3]+=a0*bb.w;
            acc[1][0]+=a1*bb.x; acc[1][1]+=a1*bb.y; acc[1][2]+=a1*bb.z; acc[1][3]+=a1*bb.w;
            acc[2][0]+=a2*bb.x; acc[2][1]+=a2*bb.y; acc[2][2]+=a2*bb.z; acc[2][3]+=a2*bb.w;
            acc[3][0]+=a3*bb.x; acc[3][1]+=a3*bb.y; acc[3][2]+=a3*bb.z; acc[3][3]+=a3*bb.w;
        }
    }

#pragma unroll
    for (int i = 0; i < 4; i++) {
        const float inv = 1.0f / l_r[i];
        const int row = q0 + ty*4 + i;
        float4 o;
        o.x = acc[i][0]*inv; o.y = acc[i][1]*inv;
        o.z = acc[i][2]*inv; o.w = acc[i][3]*inv;
        *(float4*)(og + base_bh + (size_t)row * Csz + tx*4) = o;
    }
}

// ---------------------------------------------------------------------------
extern "C" void kernel_launch(void* const* d_in, const int* in_sizes, int n_in,
                              void* d_out, int out_size)
{
    const float* x    = (const float*)d_in[0];
    const int*   mask = (const int*)  d_in[1];
    const float* W[3]   = {(const float*)d_in[2],  (const float*)d_in[8],  (const float*)d_in[14]};
    const float* Bi[3]  = {(const float*)d_in[3],  (const float*)d_in[9],  (const float*)d_in[15]};
    const float* DW[3]  = {(const float*)d_in[4],  (const float*)d_in[10], (const float*)d_in[16]};
    const float* DWB[3] = {(const float*)d_in[5],  (const float*)d_in[11], (const float*)d_in[17]};
    const float* PW[3]  = {(const float*)d_in[6],  (const float*)d_in[12], (const float*)d_in[18]};
    const float* PWB[3] = {(const float*)d_in[7],  (const float*)d_in[13], (const float*)d_in[19]};
    const float* wo = (const float*)d_in[20];
    const float* bo = (const float*)d_in[21];
    float* out = (float*)d_out;

    float *ga, *gb, *gatt;
    cudaGetSymbolAddress((void**)&ga,   g_a);
    cudaGetSymbolAddress((void**)&gb,   g_b);
    cudaGetSymbolAddress((void**)&gatt, g_att);
    const size_t PL = (size_t)Msz * Csz;

    const dim3 gg(Csz/128, Msz/128);

    // 1) q/k/v = silu(x @ W + b)
    for (int p = 0; p < 3; p++)
        sgemm_k<false, true><<<gg, 256>>>(x, W[p], Bi[p], ga + p*PL, Msz, Csz, Csz);

    // 2) depthwise conv k=3
    for (int p = 0; p < 3; p++)
        dwconv_k<<<(Msz*Csz/4)/256, 256>>>(ga + p*PL, DW[p], DWB[p], gb + p*PL);

    // 3) pointwise conv (GEMM with transposed B) + bias
    for (int p = 0; p < 3; p++)
        sgemm_k<true, false><<<gg, 256>>>(gb + p*PL, PW[p], PWB[p], ga + p*PL, Msz, Csz, Csz);

    // 4) l2norm on q, k
    l2norm_k<<<Msz, 256>>>(ga);
    l2norm_k<<<Msz, 256>>>(ga + PL);

    // 5) attention
    const size_t shmem = (size_t)(12288 + 64*65) * sizeof(float) + 64 * sizeof(int);
    cudaFuncSetAttribute(attn_k, cudaFuncAttributeMaxDynamicSharedMemorySize, (int)shmem);
    attn_k<<<dim3(Ssz/64, Bsz*Hn), 256, shmem>>>(ga, ga + PL, ga + 2*PL, mask, gatt);

    // 6) out = attn_out @ wo + bo
    sgemm_k<false, false><<<gg, 256>>>(gatt, wo, bo, out, Msz, Csz, Csz);
}

// round 3
// speedup vs baseline: 1.5384x; 1.5384x over previous
#include <cuda_runtime.h>
#include <cuda_bf16.h>
#include <math.h>
#include <cstdint>

#define Bsz 4
#define Ssz 2048
#define Csz 1024
#define Hn  16
#define Dh  64
#define Msz (Bsz*Ssz)   // 8192

// fp32 scratch
__device__ float g_a[3][(size_t)Msz*Csz];
__device__ float g_b[3][(size_t)Msz*Csz];
__device__ float g_att[(size_t)Msz*Csz];
// bf16 split scratch
__device__ __nv_bfloat16 g_ah[(size_t)Msz*Csz];
__device__ __nv_bfloat16 g_al[(size_t)Msz*Csz];
__device__ __nv_bfloat16 g_wh[(size_t)Csz*Csz];
__device__ __nv_bfloat16 g_wl[(size_t)Csz*Csz];

// ---------------------------------------------------------------------------
// PTX helpers (arch-neutral: ldmatrix / mma.sync / cp.async)
// ---------------------------------------------------------------------------
__device__ __forceinline__ uint32_t smem_u32(const void* p) {
    uint32_t a;
    asm("{ .reg .u64 t; cvta.to.shared.u64 t, %1; cvt.u32.u64 %0, t; }" : "=r"(a) : "l"(p));
    return a;
}
__device__ __forceinline__ void cp16(uint32_t saddr, const void* g) {
    asm volatile("cp.async.cg.shared.global [%0], [%1], 16;" :: "r"(saddr), "l"(g));
}
#define CP_COMMIT() asm volatile("cp.async.commit_group;" ::: "memory")
#define CP_WAIT1()  asm volatile("cp.async.wait_group 1;" ::: "memory")
#define CP_WAIT0()  asm volatile("cp.async.wait_group 0;" ::: "memory")

#define LDSM4(r, addr)                                                          \
    asm volatile("ldmatrix.sync.aligned.m8n8.x4.shared.b16 {%0,%1,%2,%3}, [%4];" \
        : "=r"((r)[0]), "=r"((r)[1]), "=r"((r)[2]), "=r"((r)[3]) : "r"(addr))
#define LDSM2(r, addr)                                                          \
    asm volatile("ldmatrix.sync.aligned.m8n8.x2.shared.b16 {%0,%1}, [%2];"      \
        : "=r"((r)[0]), "=r"((r)[1]) : "r"(addr))

#define MMA16816(d, a, b)                                                       \
    asm volatile("mma.sync.aligned.m16n8k16.row.col.f32.bf16.bf16.f32 "         \
        "{%0,%1,%2,%3}, {%4,%5,%6,%7}, {%8,%9}, {%0,%1,%2,%3};"                 \
        : "+f"((d)[0]), "+f"((d)[1]), "+f"((d)[2]), "+f"((d)[3])                \
        : "r"((a)[0]), "r"((a)[1]), "r"((a)[2]), "r"((a)[3]),                   \
          "r"((b)[0]), "r"((b)[1]))

// Swizzled smem offset for a [rows x 32] bf16 tile: row r, 16B-granule g (0..3)
__device__ __forceinline__ uint32_t tswz(int r, int g) {
    return (uint32_t)(r * 64 + ((g ^ ((r >> 1) & 3)) & 3) * 16);
}

// ---------------------------------------------------------------------------
// Split fp32 -> (hi, lo) bf16, elementwise
// ---------------------------------------------------------------------------
__global__ void split_k(const float* __restrict__ in,
                        __nv_bfloat16* __restrict__ hi, __nv_bfloat16* __restrict__ lo)
{
    const size_t i4 = (size_t)blockIdx.x * blockDim.x + threadIdx.x;
    float4 v = *(const float4*)(in + i4 * 4);
    const float* pv = &v.x;
    __nv_bfloat16 h[4], l[4];
#pragma unroll
    for (int t = 0; t < 4; t++) {
        h[t] = __float2bfloat16(pv[t]);
        l[t] = __float2bfloat16(pv[t] - __bfloat162float(h[t]));
    }
    *(__nv_bfloat162*)(hi + i4*4)     = __nv_bfloat162(h[0], h[1]);
    *(__nv_bfloat162*)(hi + i4*4 + 2) = __nv_bfloat162(h[2], h[3]);
    *(__nv_bfloat162*)(lo + i4*4)     = __nv_bfloat162(l[0], l[1]);
    *(__nv_bfloat162*)(lo + i4*4 + 2) = __nv_bfloat162(l[2], l[3]);
}

// ---------------------------------------------------------------------------
// Transpose+split: W[K,N] fp32 -> hi/lo [N,K] bf16.  32x32 tiles.
// ---------------------------------------------------------------------------
__global__ void split_trans_k(const float* __restrict__ W,
                              __nv_bfloat16* __restrict__ hi, __nv_bfloat16* __restrict__ lo,
                              int K, int N)
{
    __shared__ float t[32][33];
    const int k0 = blockIdx.y * 32, n0 = blockIdx.x * 32;
    const int tx = threadIdx.x, ty = threadIdx.y;   // (32, 8)
#pragma unroll
    for (int r = 0; r < 4; r++)
        t[ty + r*8][tx] = W[(size_t)(k0 + ty + r*8) * N + n0 + tx];
    __syncthreads();
#pragma unroll
    for (int r = 0; r < 4; r++) {
        const int n = n0 + ty + r*8, k = k0 + tx;
        const float v = t[tx][ty + r*8];
        const __nv_bfloat16 h = __float2bfloat16(v);
        hi[(size_t)n * K + k] = h;
        lo[(size_t)n * K + k] = __float2bfloat16(v - __bfloat162float(h));
    }
}

// ---------------------------------------------------------------------------
// Split-bf16 GEMM on mma.sync: C[M,N] = act(A @ B^T + bias)
// A: (Ahi,Alo)[M,K], B: (Bhi,Blo)[N,K] bf16. 128x128 tile, BK=32, 256 thr.
// 2-stage cp.async pipeline. Stage layout (32KB): Ahi|Alo|Bhi|Blo @ 8KB each.
// ---------------------------------------------------------------------------
__device__ __forceinline__ void stage_load(
    const __nv_bfloat16* __restrict__ Ahi, const __nv_bfloat16* __restrict__ Alo,
    const __nv_bfloat16* __restrict__ Bhi, const __nv_bfloat16* __restrict__ Blo,
    int K, int m0, int n0, int k0, uint32_t sb)
{
    const int t = threadIdx.x;
    const int r = t >> 1;              // 0..127
    const int g0 = (t & 1) * 2;        // 0 or 2
    const size_t arow = (size_t)(m0 + r) * K + k0;
    const size_t brow = (size_t)(n0 + r) * K + k0;
#pragma unroll
    for (int gg = 0; gg < 2; gg++) {
        const int g = g0 + gg;
        const uint32_t so = tswz(r, g);
        cp16(sb + so,         Ahi + arow + g*8);
        cp16(sb + 8192 + so,  Alo + arow + g*8);
        cp16(sb + 16384 + so, Bhi + brow + g*8);
        cp16(sb + 24576 + so, Blo + brow + g*8);
    }
}

template<int ACT>
__global__ __launch_bounds__(256, 1) void gemm_bf16_k(
    const __nv_bfloat16* __restrict__ Ahi, const __nv_bfloat16* __restrict__ Alo,
    const __nv_bfloat16* __restrict__ Bhi, const __nv_bfloat16* __restrict__ Blo,
    const float* __restrict__ bias, float* __restrict__ C,
    int M, int N, int K)
{
    extern __shared__ char sm_[];
    const uint32_t sbase = smem_u32(sm_);
    const int tid  = threadIdx.x;
    const int lane = tid & 31;
    const int warp = tid >> 5;
    const int wm = warp >> 2;          // 0..1  -> 64 rows
    const int wn = warp & 3;           // 0..3  -> 32 cols
    const int m0 = blockIdx.y * 128, n0 = blockIdx.x * 128;

    float acc[4][4][4];
#pragma unroll
    for (int i = 0; i < 4; i++)
#pragma unroll
        for (int j = 0; j < 4; j++)
#pragma unroll
            for (int c = 0; c < 4; c++) acc[i][j][c] = 0.f;

    const int NIT = K >> 5;            // 32

    stage_load(Ahi, Alo, Bhi, Blo, K, m0, n0, 0, sbase);
    CP_COMMIT();

    for (int it = 0; it < NIT; it++) {
        if (it + 1 < NIT) {
            stage_load(Ahi, Alo, Bhi, Blo, K, m0, n0, (it+1) << 5,
                       sbase + ((it+1) & 1) * 32768);
            CP_COMMIT();
            CP_WAIT1();
        } else {
            CP_WAIT0();
        }
        __syncthreads();

        const uint32_t sb = sbase + (it & 1) * 32768;
        const int lr  = lane & 15;         // A row within m16
        const int hf  = lane >> 4;         // A k-half
        const int lnb = lane & 7;          // B row within n8
        const int hfb = (lane >> 3) & 1;   // B k-half

#pragma unroll
        for (int kk = 0; kk < 2; kk++) {
            uint32_t ah[4][4], al[4][4], bh[4][2], bl[4][2];
#pragma unroll
            for (int mt = 0; mt < 4; mt++) {
                const int r = wm*64 + mt*16 + lr;
                const uint32_t off = tswz(r, kk*2 + hf);
                LDSM4(ah[mt], sb + off);
                LDSM4(al[mt], sb + 8192 + off);
            }
#pragma unroll
            for (int nt = 0; nt < 4; nt++) {
                const int rn = wn*32 + nt*8 + lnb;
                const uint32_t off = tswz(rn, kk*2 + hfb);
                LDSM2(bh[nt], sb + 16384 + off);
                LDSM2(bl[nt], sb + 24576 + off);
            }
#pragma unroll
            for (int mt = 0; mt < 4; mt++)
#pragma unroll
                for (int nt = 0; nt < 4; nt++) {
                    MMA16816(acc[mt][nt], ah[mt], bh[nt]);
                    MMA16816(acc[mt][nt], ah[mt], bl[nt]);
                    MMA16816(acc[mt][nt], al[mt], bh[nt]);
                }
        }
        __syncthreads();
    }

    // Epilogue: direct register -> global, bias + optional SiLU
    const int gid = lane >> 2;       // 0..7 row-in-tile
    const int tg  = lane & 3;        // 0..3 col pair
#pragma unroll
    for (int mt = 0; mt < 4; mt++) {
#pragma unroll
        for (int nt = 0; nt < 4; nt++) {
            const int ncol = n0 + wn*32 + nt*8 + tg*2;
            const float b0 = __ldg(&bias[ncol]);
            const float b1 = __ldg(&bias[ncol + 1]);
#pragma unroll
            for (int h = 0; h < 2; h++) {
                const int row = m0 + wm*64 + mt*16 + gid + h*8;
                float v0 = acc[mt][nt][h*2 + 0] + b0;
                float v1 = acc[mt][nt][h*2 + 1] + b1;
                if (ACT) {
                    v0 = v0 / (1.f + __expf(-v0));
                    v1 = v1 / (1.f + __expf(-v1));
                }
                float2 o = make_float2(v0, v1);
                *(float2*)(C + (size_t)row * N + ncol) = o;
            }
        }
    }
}

// ---------------------------------------------------------------------------
// Depthwise conv k=3, pad=1 over sequence. in/out: [B,S,C]. dw: [C,1,3].
// ---------------------------------------------------------------------------
__global__ void dwconv_k(const float* __restrict__ in, const float* __restrict__ dw,
                         const float* __restrict__ dwb, float* __restrict__ out)
{
    const int idx = blockIdx.x * blockDim.x + threadIdx.x;
    const int c4 = (idx & (Csz/4 - 1)) * 4;
    const int m  = idx >> 8;
    const int s  = m & (Ssz - 1);

    float4 x0 = make_float4(0,0,0,0), x2 = make_float4(0,0,0,0);
    if (s > 0)        x0 = *(const float4*)(in + (size_t)(m-1)*Csz + c4);
    const float4 x1 =      *(const float4*)(in + (size_t)m*Csz + c4);
    if (s < Ssz - 1)  x2 = *(const float4*)(in + (size_t)(m+1)*Csz + c4);

    float4 o;
    const float* p0 = &x0.x; const float* p1 = &x1.x; const float* p2 = &x2.x;
    float* po = &o.x;
#pragma unroll
    for (int t = 0; t < 4; t++) {
        const int c = c4 + t;
        po[t] = dwb[c] + dw[c*3+0]*p0[t] + dw[c*3+1]*p1[t] + dw[c*3+2]*p2[t];
    }
    *(float4*)(out + (size_t)m*Csz + c4) = o;
}

// ---------------------------------------------------------------------------
// Row-wise L2 normalize over C=1024.
// ---------------------------------------------------------------------------
__global__ void l2norm_k(float* __restrict__ buf)
{
    __shared__ float red[8];
    float* p = buf + (size_t)blockIdx.x * Csz;
    float4 v = *(float4*)(p + threadIdx.x*4);
    float ss = v.x*v.x + v.y*v.y + v.z*v.z + v.w*v.w;
#pragma unroll
    for (int off = 16; off; off >>= 1) ss += __shfl_xor_sync(0xffffffffu, ss, off);
    if ((threadIdx.x & 31) == 0) red[threadIdx.x >> 5] = ss;
    __syncthreads();
    if (threadIdx.x == 0) {
        float t = 0.f;
#pragma unroll
        for (int i = 0; i < 8; i++) t += red[i];
        red[0] = t;
    }
    __syncthreads();
    const float inv = 1.0f / fmaxf(sqrtf(red[0]), 1e-12f);
    v.x *= inv; v.y *= inv; v.z *= inv; v.w *= inv;
    *(float4*)(p + threadIdx.x*4) = v;
}

// ---------------------------------------------------------------------------
// Flash attention (fp32), unchanged.
// ---------------------------------------------------------------------------
__global__ __launch_bounds__(256) void attn_k(
    const float* __restrict__ qg, const float* __restrict__ kg,
    const float* __restrict__ vg, const int* __restrict__ mask,
    float* __restrict__ og)
{
    extern __shared__ float sm[];
    float* Qs = sm;
    float* Ks = sm + 4096;
    float* Vs = sm + 8192;
    float* Ps = sm + 12288;
    int*   Ms = (int*)(sm + 12288 + 64*65);

    const int tid = threadIdx.x;
    const int q0  = blockIdx.x * 64;
    const int b   = blockIdx.y >> 4;
    const int h   = blockIdx.y & 15;
    const size_t base_bh = ((size_t)b * Ssz) * Csz + h * Dh;

    const float* qq = qg + base_bh + (size_t)q0 * Csz;
#pragma unroll
    for (int r = 0; r < 4; r++) {
        const int f = tid + r*256;
        const int i = f >> 4, d4 = (f & 15) * 4;
        float4 v = *(const float4*)(qq + (size_t)i * Csz + d4);
        Qs[(d4+0)*64+i] = v.x; Qs[(d4+1)*64+i] = v.y;
        Qs[(d4+2)*64+i] = v.z; Qs[(d4+3)*64+i] = v.w;
    }

    const int ty = tid >> 4, tx = tid & 15;
    float m_r[4], l_r[4], acc[4][4];
#pragma unroll
    for (int i = 0; i < 4; i++) {
        m_r[i] = -1e30f; l_r[i] = 0.f;
#pragma unroll
        for (int j = 0; j < 4; j++) acc[i][j] = 0.f;
    }

    for (int k0 = 0; k0 < Ssz; k0 += 64) {
        __syncthreads();
        const float* kk_ = kg + base_bh + (size_t)k0 * Csz;
        const float* vv_ = vg + base_bh + (size_t)k0 * Csz;
#pragma unroll
        for (int r = 0; r < 4; r++) {
            const int f = tid + r*256;
            const int i = f >> 4, d4 = (f & 15) * 4;
            float4 kv = *(const float4*)(kk_ + (size_t)i * Csz + d4);
            Ks[(d4+0)*64+i] = kv.x; Ks[(d4+1)*64+i] = kv.y;
            Ks[(d4+2)*64+i] = kv.z; Ks[(d4+3)*64+i] = kv.w;
            float4 vv = *(const float4*)(vv_ + (size_t)i * Csz + d4);
            *(float4*)&Vs[i*64 + d4] = vv;
        }
        if (tid < 64) Ms[tid] = mask[(size_t)b * Ssz + k0 + tid];
        __syncthreads();

        float s[4][4];
#pragma unroll
        for (int i = 0; i < 4; i++)
#pragma unroll
            for (int j = 0; j < 4; j++) s[i][j] = 0.f;
#pragma unroll 16
        for (int d = 0; d < 64; d++) {
            const float a0 = Qs[d*64 + ty*4 + 0];
            const float a1 = Qs[d*64 + ty*4 + 1];
            const float a2 = Qs[d*64 + ty*4 + 2];
            const float a3 = Qs[d*64 + ty*4 + 3];
            const float4 bb = *(const float4*)&Ks[d*64 + tx*4];
            s[0][0]+=a0*bb.x; s[0][1]+=a0*bb.y; s[0][2]+=a0*bb.z; s[0][3]+=a0*bb.w;
            s[1][0]+=a1*bb.x; s[1][1]+=a1*bb.y; s[1][2]+=a1*bb.z; s[1][3]+=a1*bb.w;
            s[2][0]+=a2*bb.x; s[2][1]+=a2*bb.y; s[2][2]+=a2*bb.z; s[2][3]+=a2*bb.w;
            s[3][0]+=a3*bb.x; s[3][1]+=a3*bb.y; s[3][2]+=a3*bb.z; s[3][3]+=a3*bb.w;
        }
#pragma unroll
        for (int j = 0; j < 4; j++) {
            const bool mk = (Ms[tx*4 + j] != 0);
#pragma unroll
            for (int i = 0; i < 4; i++)
                s[i][j] = mk ? s[i][j] * 0.125f : -1e30f;
        }

#pragma unroll
        for (int i = 0; i < 4; i++) {
            float rm = fmaxf(fmaxf(s[i][0], s[i][1]), fmaxf(s[i][2], s[i][3]));
            rm = fmaxf(rm, __shfl_xor_sync(0xffffffffu, rm, 1));
            rm = fmaxf(rm, __shfl_xor_sync(0xffffffffu, rm, 2));
            rm = fmaxf(rm, __shfl_xor_sync(0xffffffffu, rm, 4));
            rm = fmaxf(rm, __shfl_xor_sync(0xffffffffu, rm, 8));
            const float mnew = fmaxf(m_r[i], rm);
            const float corr = __expf(m_r[i] - mnew);
            float rs = 0.f;
#pragma unroll
            for (int j = 0; j < 4; j++) {
                const float p = __expf(s[i][j] - mnew);
                s[i][j] = p;
                rs += p;
            }
            rs += __shfl_xor_sync(0xffffffffu, rs, 1);
            rs += __shfl_xor_sync(0xffffffffu, rs, 2);
            rs += __shfl_xor_sync(0xffffffffu, rs, 4);
            rs += __shfl_xor_sync(0xffffffffu, rs, 8);
            l_r[i] = l_r[i] * corr + rs;
            m_r[i] = mnew;
#pragma unroll
            for (int j = 0; j < 4; j++) acc[i][j] *= corr;
#pragma unroll
            for (int j = 0; j < 4; j++)
                Ps[(tx*4 + j)*65 + ty*4 + i] = s[i][j];
        }
        __syncthreads();

#pragma unroll 16
        for (int j = 0; j < 64; j++) {
            const float a0 = Ps[j*65 + ty*4 + 0];
            const float a1 = Ps[j*65 + ty*4 + 1];
            const float a2 = Ps[j*65 + ty*4 + 2];
            const float a3 = Ps[j*65 + ty*4 + 3];
            const float4 bb = *(const float4*)&Vs[j*64 + tx*4];
            acc[0][0]+=a0*bb.x; acc[0][1]+=a0*bb.y; acc[0][2]+=a0*bb.z; acc[0][3]+=a0*bb.w;
            acc[1][0]+=a1*bb.x; acc[1][1]+=a1*bb.y; acc[1][2]+=a1*bb.z; acc[1][3]+=a1*bb.w;
            acc[2][0]+=a2*bb.x; acc[2][1]+=a2*bb.y; acc[2][2]+=a2*bb.z; acc[2][3]+=a2*bb.w;
            acc[3][0]+=a3*bb.x; acc[3][1]+=a3*bb.y; acc[3][2]+=a3*bb.z; acc[3][3]+=a3*bb.w;
        }
    }

#pragma unroll
    for (int i = 0; i < 4; i++) {
        const float inv = 1.0f / l_r[i];
        const int row = q0 + ty*4 + i;
        float4 o;
        o.x = acc[i][0]*inv; o.y = acc[i][1]*inv;
        o.z = acc[i][2]*inv; o.w = acc[i][3]*inv;
        *(float4*)(og + base_bh + (size_t)row * Csz + tx*4) = o;
    }
}

// ---------------------------------------------------------------------------
extern "C" void kernel_launch(void* const* d_in, const int* in_sizes, int n_in,
                              void* d_out, int out_size)
{
    const float* x    = (const float*)d_in[0];
    const int*   mask = (const int*)  d_in[1];
    const float* W[3]   = {(const float*)d_in[2],  (const float*)d_in[8],  (const float*)d_in[14]};
    const float* Bi[3]  = {(const float*)d_in[3],  (const float*)d_in[9],  (const float*)d_in[15]};
    const float* DW[3]  = {(const float*)d_in[4],  (const float*)d_in[10], (const float*)d_in[16]};
    const float* DWB[3] = {(const float*)d_in[5],  (const float*)d_in[11], (const float*)d_in[17]};
    const float* PW[3]  = {(const float*)d_in[6],  (const float*)d_in[12], (const float*)d_in[18]};
    const float* PWB[3] = {(const float*)d_in[7],  (const float*)d_in[13], (const float*)d_in[19]};
    const float* wo = (const float*)d_in[20];
    const float* bo = (const float*)d_in[21];
    float* out = (float*)d_out;

    float *ga, *gb, *gatt;
    __nv_bfloat16 *ah, *al, *wh, *wl;
    cudaGetSymbolAddress((void**)&ga,   g_a);
    cudaGetSymbolAddress((void**)&gb,   g_b);
    cudaGetSymbolAddress((void**)&gatt, g_att);
    cudaGetSymbolAddress((void**)&ah,   g_ah);
    cudaGetSymbolAddress((void**)&al,   g_al);
    cudaGetSymbolAddress((void**)&wh,   g_wh);
    cudaGetSymbolAddress((void**)&wl,   g_wl);
    const size_t PL = (size_t)Msz * Csz;

    const int GEMM_SMEM = 65536;
    cudaFuncSetAttribute(gemm_bf16_k<0>, cudaFuncAttributeMaxDynamicSharedMemorySize, GEMM_SMEM);
    cudaFuncSetAttribute(gemm_bf16_k<1>, cudaFuncAttributeMaxDynamicSharedMemorySize, GEMM_SMEM);
    const size_t ash = (size_t)(12288 + 64*65) * sizeof(float) + 64 * sizeof(int);
    cudaFuncSetAttribute(attn_k, cudaFuncAttributeMaxDynamicSharedMemorySize, (int)ash);

    const dim3 ggemm(Csz/128, Msz/128);
    const dim3 gtr(Csz/32, Csz/32), btr(32, 8);

    // 1) split x once
    split_k<<<(Msz*Csz/4)/256, 256>>>(x, ah, al);

    // 2) q/k/v = silu(x @ W + b)
    for (int p = 0; p < 3; p++) {
        split_trans_k<<<gtr, btr>>>(W[p], wh, wl, Csz, Csz);
        gemm_bf16_k<1><<<ggemm, 256, GEMM_SMEM>>>(ah, al, wh, wl, Bi[p], ga + p*PL, Msz, Csz, Csz);
    }

    // 3) depthwise conv
    for (int p = 0; p < 3; p++)
        dwconv_k<<<(Msz*Csz/4)/256, 256>>>(ga + p*PL, DW[p], DWB[p], gb + p*PL);

    // 4) pointwise conv: PW is [N,K] already (out-ch major)
    for (int p = 0; p < 3; p++) {
        split_k<<<(Msz*Csz/4)/256, 256>>>(gb + p*PL, ah, al);
        split_k<<<(Csz*Csz/4)/256, 256>>>(PW[p], wh, wl);
        gemm_bf16_k<0><<<ggemm, 256, GEMM_SMEM>>>(ah, al, wh, wl, PWB[p], ga + p*PL, Msz, Csz, Csz);
    }

    // 5) l2norm q, k
    l2norm_k<<<Msz, 256>>>(ga);
    l2norm_k<<<Msz, 256>>>(ga + PL);

    // 6) attention (fp32)
    attn_k<<<dim3(Ssz/64, Bsz*Hn), 256, ash>>>(ga, ga + PL, ga + 2*PL, mask, gatt);

    // 7) out = attn_out @ wo + bo
    split_k<<<(Msz*Csz/4)/256, 256>>>(gatt, ah, al);
    split_trans_k<<<gtr, btr>>>(wo, wh, wl, Csz, Csz);
    gemm_bf16_k<0><<<ggemm, 256, GEMM_SMEM>>>(ah, al, wh, wl, bo, out, Msz, Csz, Csz);
}

// round 5
// speedup vs baseline: 3.1851x; 2.0703x over previous
#include <cuda_runtime.h>
#include <cuda_bf16.h>
#include <math.h>
#include <cstdint>

#define Bsz 4
#define Ssz 2048
#define Csz 1024
#define Hn  16
#define Dh  64
#define Msz (Bsz*Ssz)   // 8192

// fp32 scratch
__device__ float g_a[3][(size_t)Msz*Csz];
__device__ float g_b[3][(size_t)Msz*Csz];
__device__ float g_att[(size_t)Msz*Csz];
// bf16 scratch
__device__ __nv_bfloat16 g_ah[(size_t)Msz*Csz];
__device__ __nv_bfloat16 g_al[(size_t)Msz*Csz];
__device__ __nv_bfloat16 g_vb[(size_t)Msz*Csz];   // V^T per (b,h): [d][s]
__device__ __nv_bfloat16 g_wh[(size_t)Csz*Csz];
__device__ __nv_bfloat16 g_wl[(size_t)Csz*Csz];

// ---------------------------------------------------------------------------
// PTX helpers (arch-neutral: ldmatrix / mma.sync / cp.async)
// ---------------------------------------------------------------------------
__device__ __forceinline__ uint32_t smem_u32(const void* p) {
    uint32_t a;
    asm("{ .reg .u64 t; cvta.to.shared.u64 t, %1; cvt.u32.u64 %0, t; }" : "=r"(a) : "l"(p));
    return a;
}
__device__ __forceinline__ void cp16(uint32_t saddr, const void* g) {
    asm volatile("cp.async.cg.shared.global [%0], [%1], 16;" :: "r"(saddr), "l"(g));
}
__device__ __forceinline__ void cp4(uint32_t saddr, const void* g) {
    asm volatile("cp.async.ca.shared.global [%0], [%1], 4;" :: "r"(saddr), "l"(g));
}
#define CP_COMMIT() asm volatile("cp.async.commit_group;" ::: "memory")
#define CP_WAIT1()  asm volatile("cp.async.wait_group 1;" ::: "memory")
#define CP_WAIT0()  asm volatile("cp.async.wait_group 0;" ::: "memory")

#define LDSM4(r, addr)                                                          \
    asm volatile("ldmatrix.sync.aligned.m8n8.x4.shared.b16 {%0,%1,%2,%3}, [%4];" \
        : "=r"((r)[0]), "=r"((r)[1]), "=r"((r)[2]), "=r"((r)[3]) : "r"(addr))
#define LDSM2(r, addr)                                                          \
    asm volatile("ldmatrix.sync.aligned.m8n8.x2.shared.b16 {%0,%1}, [%2];"      \
        : "=r"((r)[0]), "=r"((r)[1]) : "r"(addr))

#define MMA16816(d, a, b)                                                       \
    asm volatile("mma.sync.aligned.m16n8k16.row.col.f32.bf16.bf16.f32 "         \
        "{%0,%1,%2,%3}, {%4,%5,%6,%7}, {%8,%9}, {%0,%1,%2,%3};"                 \
        : "+f"((d)[0]), "+f"((d)[1]), "+f"((d)[2]), "+f"((d)[3])                \
        : "r"((a)[0]), "r"((a)[1]), "r"((a)[2]), "r"((a)[3]),                   \
          "r"((b)[0]), "r"((b)[1]))

__device__ __forceinline__ uint32_t pack_bf16(float lo, float hi) {
    uint32_t r;
    asm("cvt.rn.bf16x2.f32 %0, %1, %2;" : "=r"(r) : "f"(hi), "f"(lo));
    return r;
}

// Swizzled smem offset for a [rows x 32] bf16 tile (64B rows): granule g 0..3
__device__ __forceinline__ uint32_t tswz(int r, int g) {
    return (uint32_t)(r * 64 + ((g ^ ((r >> 1) & 3)) & 3) * 16);
}
// Swizzled offset for 128B rows (64 bf16): granule g 0..7
__device__ __forceinline__ uint32_t tswz128(int r, int g) {
    return (uint32_t)(r * 128 + ((g ^ (r & 7)) & 7) * 16);
}

// ---------------------------------------------------------------------------
// Split fp32 -> (hi, lo) bf16
// ---------------------------------------------------------------------------
__global__ void split_k(const float* __restrict__ in,
                        __nv_bfloat16* __restrict__ hi, __nv_bfloat16* __restrict__ lo)
{
    const size_t i4 = (size_t)blockIdx.x * blockDim.x + threadIdx.x;
    float4 v = *(const float4*)(in + i4 * 4);
    const float* pv = &v.x;
    __nv_bfloat16 h[4], l[4];
#pragma unroll
    for (int t = 0; t < 4; t++) {
        h[t] = __float2bfloat16(pv[t]);
        l[t] = __float2bfloat16(pv[t] - __bfloat162float(h[t]));
    }
    *(__nv_bfloat162*)(hi + i4*4)     = __nv_bfloat162(h[0], h[1]);
    *(__nv_bfloat162*)(hi + i4*4 + 2) = __nv_bfloat162(h[2], h[3]);
    *(__nv_bfloat162*)(lo + i4*4)     = __nv_bfloat162(l[0], l[1]);
    *(__nv_bfloat162*)(lo + i4*4 + 2) = __nv_bfloat162(l[2], l[3]);
}

// ---------------------------------------------------------------------------
// Transpose+split: W[K,N] fp32 -> hi/lo [N,K] bf16.
// ---------------------------------------------------------------------------
__global__ void split_trans_k(const float* __restrict__ W,
                              __nv_bfloat16* __restrict__ hi, __nv_bfloat16* __restrict__ lo,
                              int K, int N)
{
    __shared__ float t[32][33];
    const int k0 = blockIdx.y * 32, n0 = blockIdx.x * 32;
    const int tx = threadIdx.x, ty = threadIdx.y;
#pragma unroll
    for (int r = 0; r < 4; r++)
        t[ty + r*8][tx] = W[(size_t)(k0 + ty + r*8) * N + n0 + tx];
    __syncthreads();
#pragma unroll
    for (int r = 0; r < 4; r++) {
        const int n = n0 + ty + r*8, k = k0 + tx;
        const float v = t[tx][ty + r*8];
        const __nv_bfloat16 h = __float2bfloat16(v);
        hi[(size_t)n * K + k] = h;
        lo[(size_t)n * K + k] = __float2bfloat16(v - __bfloat162float(h));
    }
}

// ---------------------------------------------------------------------------
// V transpose to bf16: in [B,S,C] fp32 -> vt[(bh*64 + d)*Ssz + s] bf16
// ---------------------------------------------------------------------------
__global__ void vtrans_k(const float* __restrict__ in, __nv_bfloat16* __restrict__ vt)
{
    __shared__ float t[32][33];
    const int z = blockIdx.y;
    const int dblk = z & 1, bh = z >> 1;
    const int b = bh >> 4, h = bh & 15;
    const int s0 = blockIdx.x * 32;
    const int tx = threadIdx.x, ty = threadIdx.y;
#pragma unroll
    for (int r = 0; r < 4; r++)
        t[ty + r*8][tx] = in[(size_t)(b*Ssz + s0 + ty + r*8) * Csz + h*Dh + dblk*32 + tx];
    __syncthreads();
#pragma unroll
    for (int r = 0; r < 4; r++) {
        const int d = dblk*32 + ty + r*8;
        vt[((size_t)bh * Dh + d) * Ssz + s0 + tx] = __float2bfloat16(t[tx][ty + r*8]);
    }
}

// ---------------------------------------------------------------------------
// Split-bf16 GEMM on mma.sync (unchanged from round 3, passing)
// ---------------------------------------------------------------------------
__device__ __forceinline__ void stage_load(
    const __nv_bfloat16* __restrict__ Ahi, const __nv_bfloat16* __restrict__ Alo,
    const __nv_bfloat16* __restrict__ Bhi, const __nv_bfloat16* __restrict__ Blo,
    int K, int m0, int n0, int k0, uint32_t sb)
{
    const int t = threadIdx.x;
    const int r = t >> 1;
    const int g0 = (t & 1) * 2;
    const size_t arow = (size_t)(m0 + r) * K + k0;
    const size_t brow = (size_t)(n0 + r) * K + k0;
#pragma unroll
    for (int gg = 0; gg < 2; gg++) {
        const int g = g0 + gg;
        const uint32_t so = tswz(r, g);
        cp16(sb + so,         Ahi + arow + g*8);
        cp16(sb + 8192 + so,  Alo + arow + g*8);
        cp16(sb + 16384 + so, Bhi + brow + g*8);
        cp16(sb + 24576 + so, Blo + brow + g*8);
    }
}

template<int ACT>
__global__ __launch_bounds__(256, 1) void gemm_bf16_k(
    const __nv_bfloat16* __restrict__ Ahi, const __nv_bfloat16* __restrict__ Alo,
    const __nv_bfloat16* __restrict__ Bhi, const __nv_bfloat16* __restrict__ Blo,
    const float* __restrict__ bias, float* __restrict__ C,
    int M, int N, int K)
{
    extern __shared__ char sm_[];
    const uint32_t sbase = smem_u32(sm_);
    const int tid  = threadIdx.x;
    const int lane = tid & 31;
    const int warp = tid >> 5;
    const int wm = warp >> 2;
    const int wn = warp & 3;
    const int m0 = blockIdx.y * 128, n0 = blockIdx.x * 128;

    float acc[4][4][4];
#pragma unroll
    for (int i = 0; i < 4; i++)
#pragma unroll
        for (int j = 0; j < 4; j++)
#pragma unroll
            for (int c = 0; c < 4; c++) acc[i][j][c] = 0.f;

    const int NIT = K >> 5;

    stage_load(Ahi, Alo, Bhi, Blo, K, m0, n0, 0, sbase);
    CP_COMMIT();

    for (int it = 0; it < NIT; it++) {
        if (it + 1 < NIT) {
            stage_load(Ahi, Alo, Bhi, Blo, K, m0, n0, (it+1) << 5,
                       sbase + ((it+1) & 1) * 32768);
            CP_COMMIT();
            CP_WAIT1();
        } else {
            CP_WAIT0();
        }
        __syncthreads();

        const uint32_t sb = sbase + (it & 1) * 32768;
        const int lr  = lane & 15;
        const int hf  = lane >> 4;
        const int lnb = lane & 7;
        const int hfb = (lane >> 3) & 1;

#pragma unroll
        for (int kk = 0; kk < 2; kk++) {
            uint32_t ah[4][4], al[4][4], bh[4][2], bl[4][2];
#pragma unroll
            for (int mt = 0; mt < 4; mt++) {
                const int r = wm*64 + mt*16 + lr;
                const uint32_t off = tswz(r, kk*2 + hf);
                LDSM4(ah[mt], sb + off);
                LDSM4(al[mt], sb + 8192 + off);
            }
#pragma unroll
            for (int nt = 0; nt < 4; nt++) {
                const int rn = wn*32 + nt*8 + lnb;
                const uint32_t off = tswz(rn, kk*2 + hfb);
                LDSM2(bh[nt], sb + 16384 + off);
                LDSM2(bl[nt], sb + 24576 + off);
            }
#pragma unroll
            for (int mt = 0; mt < 4; mt++)
#pragma unroll
                for (int nt = 0; nt < 4; nt++) {
                    MMA16816(acc[mt][nt], ah[mt], bh[nt]);
                    MMA16816(acc[mt][nt], ah[mt], bl[nt]);
                    MMA16816(acc[mt][nt], al[mt], bh[nt]);
                }
        }
        __syncthreads();
    }

    const int gid = lane >> 2;
    const int tg  = lane & 3;
#pragma unroll
    for (int mt = 0; mt < 4; mt++) {
#pragma unroll
        for (int nt = 0; nt < 4; nt++) {
            const int ncol = n0 + wn*32 + nt*8 + tg*2;
            const float b0 = __ldg(&bias[ncol]);
            const float b1 = __ldg(&bias[ncol + 1]);
#pragma unroll
            for (int h = 0; h < 2; h++) {
                const int row = m0 + wm*64 + mt*16 + gid + h*8;
                float v0 = acc[mt][nt][h*2 + 0] + b0;
                float v1 = acc[mt][nt][h*2 + 1] + b1;
                if (ACT) {
                    v0 = v0 / (1.f + __expf(-v0));
                    v1 = v1 / (1.f + __expf(-v1));
                }
                float2 o = make_float2(v0, v1);
                *(float2*)(C + (size_t)row * N + ncol) = o;
            }
        }
    }
}

// ---------------------------------------------------------------------------
// Depthwise conv k=3
// ---------------------------------------------------------------------------
__global__ void dwconv_k(const float* __restrict__ in, const float* __restrict__ dw,
                         const float* __restrict__ dwb, float* __restrict__ out)
{
    const int idx = blockIdx.x * blockDim.x + threadIdx.x;
    const int c4 = (idx & (Csz/4 - 1)) * 4;
    const int m  = idx >> 8;
    const int s  = m & (Ssz - 1);

    float4 x0 = make_float4(0,0,0,0), x2 = make_float4(0,0,0,0);
    if (s > 0)        x0 = *(const float4*)(in + (size_t)(m-1)*Csz + c4);
    const float4 x1 =      *(const float4*)(in + (size_t)m*Csz + c4);
    if (s < Ssz - 1)  x2 = *(const float4*)(in + (size_t)(m+1)*Csz + c4);

    float4 o;
    const float* p0 = &x0.x; const float* p1 = &x1.x; const float* p2 = &x2.x;
    float* po = &o.x;
#pragma unroll
    for (int t = 0; t < 4; t++) {
        const int c = c4 + t;
        po[t] = dwb[c] + dw[c*3+0]*p0[t] + dw[c*3+1]*p1[t] + dw[c*3+2]*p2[t];
    }
    *(float4*)(out + (size_t)m*Csz + c4) = o;
}

// ---------------------------------------------------------------------------
// L2 normalize over C=1024, output bf16.
// ---------------------------------------------------------------------------
__global__ void l2norm_bf16_k(const float* __restrict__ src, __nv_bfloat16* __restrict__ dst)
{
    __shared__ float red[8];
    const float* p = src + (size_t)blockIdx.x * Csz;
    float4 v = *(const float4*)(p + threadIdx.x*4);
    float ss = v.x*v.x + v.y*v.y + v.z*v.z + v.w*v.w;
#pragma unroll
    for (int off = 16; off; off >>= 1) ss += __shfl_xor_sync(0xffffffffu, ss, off);
    if ((threadIdx.x & 31) == 0) red[threadIdx.x >> 5] = ss;
    __syncthreads();
    if (threadIdx.x == 0) {
        float t = 0.f;
#pragma unroll
        for (int i = 0; i < 8; i++) t += red[i];
        red[0] = t;
    }
    __syncthreads();
    const float inv = 1.0f / fmaxf(sqrtf(red[0]), 1e-12f);
    __nv_bfloat16* d = dst + (size_t)blockIdx.x * Csz + threadIdx.x*4;
    *(__nv_bfloat162*)(d)     = __nv_bfloat162(__float2bfloat16(v.x*inv), __float2bfloat16(v.y*inv));
    *(__nv_bfloat162*)(d + 2) = __nv_bfloat162(__float2bfloat16(v.z*inv), __float2bfloat16(v.w*inv));
}

// ---------------------------------------------------------------------------
// Flash attention on mma.sync (bf16 in, fp32 accum).
// Block: 128 queries x (b,h). 8 warps of 16 q-rows. K/V chunks of 64,
// double-buffered cp.async. Stage = K(8KB) + V^T(8KB) + mask(256B) = 16640B.
// ---------------------------------------------------------------------------
#define ATT_STG 16640
__device__ __forceinline__ void attn_stage(
    const __nv_bfloat16* __restrict__ kb, const __nv_bfloat16* __restrict__ vt,
    const int* __restrict__ mask, size_t qkbase, size_t vbase, int b,
    int chunk, uint32_t st)
{
    const int tid = threadIdx.x;
#pragma unroll
    for (int i = 0; i < 2; i++) {
        const int idx = tid + i*256;
        const int r = idx >> 3, g = idx & 7;
        const uint32_t so = tswz128(r, g);
        cp16(st + so,        kb + qkbase + (size_t)(chunk*64 + r) * Csz + g*8);
        cp16(st + 8192 + so, vt + vbase + (size_t)r * Ssz + chunk*64 + g*8);
    }
    if (tid < 64)
        cp4(st + 16384 + tid*4, mask + (size_t)b * Ssz + chunk*64 + tid);
}

__global__ __launch_bounds__(256, 1) void attn2_k(
    const __nv_bfloat16* __restrict__ qb, const __nv_bfloat16* __restrict__ kb,
    const __nv_bfloat16* __restrict__ vt, const int* __restrict__ mask,
    float* __restrict__ og)
{
    extern __shared__ char sm_[];
    const uint32_t sbase = smem_u32(sm_);
    const int tid = threadIdx.x, lane = tid & 31, warp = tid >> 5;
    const int q0 = blockIdx.x * 128;
    const int bh = blockIdx.y;
    const int b = bh >> 4, h = bh & 15;

    const size_t qkbase = ((size_t)b * Ssz) * Csz + h * Dh;
    const size_t vbase  = (size_t)bh * Dh * Ssz;

    // Q -> smem (128 rows x 128B)
#pragma unroll
    for (int i = 0; i < 4; i++) {
        const int idx = tid + i*256;
        const int r = idx >> 3, g = idx & 7;
        cp16(sbase + tswz128(r, g), qb + qkbase + (size_t)(q0 + r) * Csz + g*8);
    }
    CP_COMMIT();

    const uint32_t kvb = sbase + 16384;
    attn_stage(kb, vt, mask, qkbase, vbase, b, 0, kvb);
    CP_COMMIT();

    float oacc[8][4];
#pragma unroll
    for (int nt = 0; nt < 8; nt++)
#pragma unroll
        for (int c = 0; c < 4; c++) oacc[nt][c] = 0.f;
    float m0 = -1e30f, m1 = -1e30f, l0 = 0.f, l1 = 0.f;
    uint32_t aq[4][4];

    const int cb = (lane & 3) * 2;

    for (int it = 0; it < Ssz/64; it++) {
        if (it + 1 < Ssz/64) {
            attn_stage(kb, vt, mask, qkbase, vbase, b, it+1, kvb + ((it+1)&1)*ATT_STG);
            CP_COMMIT();
            CP_WAIT1();
        } else {
            CP_WAIT0();
        }
        __syncthreads();

        if (it == 0) {
#pragma unroll
            for (int ks = 0; ks < 4; ks++) {
                const int r = warp*16 + (lane & 15);
                const int g = ks*2 + (lane >> 4);
                LDSM4(aq[ks], sbase + tswz128(r, g));
            }
        }

        const uint32_t st = kvb + (it & 1) * ATT_STG;
        const int* Ms = (const int*)(sm_ + 16384 + (it & 1) * ATT_STG + 16384);

        // S = Q K^T
        float sacc[8][4];
#pragma unroll
        for (int nt = 0; nt < 8; nt++)
#pragma unroll
            for (int c = 0; c < 4; c++) sacc[nt][c] = 0.f;

#pragma unroll
        for (int ks = 0; ks < 4; ks++) {
#pragma unroll
            for (int nt = 0; nt < 8; nt++) {
                uint32_t kf[2];
                const int r = nt*8 + (lane & 7);
                const int g = ks*2 + ((lane >> 3) & 1);
                LDSM2(kf, st + tswz128(r, g));
                MMA16816(sacc[nt], aq[ks], kf);
            }
        }

        // scale + mask + online softmax (rows lane>>2 and +8)
        float mx0 = -1e30f, mx1 = -1e30f;
#pragma unroll
        for (int nt = 0; nt < 8; nt++) {
            const int c = nt*8 + cb;
            const bool k0m = Ms[c] != 0, k1m = Ms[c+1] != 0;
            sacc[nt][0] = k0m ? sacc[nt][0]*0.125f : -1e30f;
            sacc[nt][1] = k1m ? sacc[nt][1]*0.125f : -1e30f;
            sacc[nt][2] = k0m ? sacc[nt][2]*0.125f : -1e30f;
            sacc[nt][3] = k1m ? sacc[nt][3]*0.125f : -1e30f;
            mx0 = fmaxf(mx0, fmaxf(sacc[nt][0], sacc[nt][1]));
            mx1 = fmaxf(mx1, fmaxf(sacc[nt][2], sacc[nt][3]));
        }
        mx0 = fmaxf(mx0, __shfl_xor_sync(0xffffffffu, mx0, 1));
        mx0 = fmaxf(mx0, __shfl_xor_sync(0xffffffffu, mx0, 2));
        mx1 = fmaxf(mx1, __shfl_xor_sync(0xffffffffu, mx1, 1));
        mx1 = fmaxf(mx1, __shfl_xor_sync(0xffffffffu, mx1, 2));
        const float mn0 = fmaxf(m0, mx0), mn1 = fmaxf(m1, mx1);
        const float c0 = __expf(m0 - mn0), c1 = __expf(m1 - mn1);
        m0 = mn0; m1 = mn1;
        float rs0 = 0.f, rs1 = 0.f;
#pragma unroll
        for (int nt = 0; nt < 8; nt++) {
            sacc[nt][0] = __expf(sacc[nt][0] - mn0);
            sacc[nt][1] = __expf(sacc[nt][1] - mn0);
            sacc[nt][2] = __expf(sacc[nt][2] - mn1);
            sacc[nt][3] = __expf(sacc[nt][3] - mn1);
            rs0 += sacc[nt][0] + sacc[nt][1];
            rs1 += sacc[nt][2] + sacc[nt][3];
        }
        rs0 += __shfl_xor_sync(0xffffffffu, rs0, 1);
        rs0 += __shfl_xor_sync(0xffffffffu, rs0, 2);
        rs1 += __shfl_xor_sync(0xffffffffu, rs1, 1);
        rs1 += __shfl_xor_sync(0xffffffffu, rs1, 2);
        l0 = l0*c0 + rs0;
        l1 = l1*c1 + rs1;
#pragma unroll
        for (int nt = 0; nt < 8; nt++) {
            oacc[nt][0] *= c0; oacc[nt][1] *= c0;
            oacc[nt][2] *= c1; oacc[nt][3] *= c1;
        }

        // O += P V  (P A-frags straight from sacc registers; B from V^T smem)
#pragma unroll
        for (int ks = 0; ks < 4; ks++) {
            uint32_t pa[4];
            pa[0] = pack_bf16(sacc[2*ks][0],   sacc[2*ks][1]);
            pa[1] = pack_bf16(sacc[2*ks][2],   sacc[2*ks][3]);
            pa[2] = pack_bf16(sacc[2*ks+1][0], sacc[2*ks+1][1]);
            pa[3] = pack_bf16(sacc[2*ks+1][2], sacc[2*ks+1][3]);
#pragma unroll
            for (int nt = 0; nt < 8; nt++) {
                uint32_t vf[2];
                const int r = nt*8 + (lane & 7);
                const int g = ks*2 + ((lane >> 3) & 1);
                LDSM2(vf, st + 8192 + tswz128(r, g));
                MMA16816(oacc[nt], pa, vf);
            }
        }
        __syncthreads();
    }

    // Epilogue
    const float inv0 = 1.f / l0, inv1 = 1.f / l1;
    const int r0 = q0 + warp*16 + (lane >> 2);
#pragma unroll
    for (int nt = 0; nt < 8; nt++) {
        const int c = h*Dh + nt*8 + cb;
        *(float2*)(og + ((size_t)b*Ssz + r0) * Csz + c) =
            make_float2(oacc[nt][0]*inv0, oacc[nt][1]*inv0);
        *(float2*)(og + ((size_t)b*Ssz + r0 + 8) * Csz + c) =
            make_float2(oacc[nt][2]*inv1, oacc[nt][3]*inv1);
    }
}

// ---------------------------------------------------------------------------
extern "C" void kernel_launch(void* const* d_in, const int* in_sizes, int n_in,
                              void* d_out, int out_size)
{
    const float* x    = (const float*)d_in[0];
    const int*   mask = (const int*)  d_in[1];
    const float* W[3]   = {(const float*)d_in[2],  (const float*)d_in[8],  (const float*)d_in[14]};
    const float* Bi[3]  = {(const float*)d_in[3],  (const float*)d_in[9],  (const float*)d_in[15]};
    const float* DW[3]  = {(const float*)d_in[4],  (const float*)d_in[10], (const float*)d_in[16]};
    const float* DWB[3] = {(const float*)d_in[5],  (const float*)d_in[11], (const float*)d_in[17]};
    const float* PW[3]  = {(const float*)d_in[6],  (const float*)d_in[12], (const float*)d_in[18]};
    const float* PWB[3] = {(const float*)d_in[7],  (const float*)d_in[13], (const float*)d_in[19]};
    const float* wo = (const float*)d_in[20];
    const float* bo = (const float*)d_in[21];
    float* out = (float*)d_out;

    float *ga, *gb, *gatt;
    __nv_bfloat16 *ah, *al, *vb, *wh, *wl;
    cudaGetSymbolAddress((void**)&ga,   g_a);
    cudaGetSymbolAddress((void**)&gb,   g_b);
    cudaGetSymbolAddress((void**)&gatt, g_att);
    cudaGetSymbolAddress((void**)&ah,   g_ah);
    cudaGetSymbolAddress((void**)&al,   g_al);
    cudaGetSymbolAddress((void**)&vb,   g_vb);
    cudaGetSymbolAddress((void**)&wh,   g_wh);
    cudaGetSymbolAddress((void**)&wl,   g_wl);
    const size_t PL = (size_t)Msz * Csz;

    const int GEMM_SMEM = 65536;
    const int ATT_SMEM  = 16384 + 2*ATT_STG;   // 49664
    cudaFuncSetAttribute(gemm_bf16_k<0>, cudaFuncAttributeMaxDynamicSharedMemorySize, GEMM_SMEM);
    cudaFuncSetAttribute(gemm_bf16_k<1>, cudaFuncAttributeMaxDynamicSharedMemorySize, GEMM_SMEM);
    cudaFuncSetAttribute(attn2_k, cudaFuncAttributeMaxDynamicSharedMemorySize, ATT_SMEM);

    const dim3 ggemm(Csz/128, Msz/128);
    const dim3 gtr(Csz/32, Csz/32), btr(32, 8);

    // 1) split x once
    split_k<<<(Msz*Csz/4)/256, 256>>>(x, ah, al);

    // 2) q/k/v = silu(x @ W + b)
    for (int p = 0; p < 3; p++) {
        split_trans_k<<<gtr, btr>>>(W[p], wh, wl, Csz, Csz);
        gemm_bf16_k<1><<<ggemm, 256, GEMM_SMEM>>>(ah, al, wh, wl, Bi[p], ga + p*PL, Msz, Csz, Csz);
    }

    // 3) depthwise conv
    for (int p = 0; p < 3; p++)
        dwconv_k<<<(Msz*Csz/4)/256, 256>>>(ga + p*PL, DW[p], DWB[p], gb + p*PL);

    // 4) pointwise conv (PW already [N,K])
    for (int p = 0; p < 3; p++) {
        split_k<<<(Msz*Csz/4)/256, 256>>>(gb + p*PL, ah, al);
        split_k<<<(Csz*Csz/4)/256, 256>>>(PW[p], wh, wl);
        gemm_bf16_k<0><<<ggemm, 256, GEMM_SMEM>>>(ah, al, wh, wl, PWB[p], ga + p*PL, Msz, Csz, Csz);
    }

    // 5) l2norm q,k -> bf16; V -> bf16 transposed
    l2norm_bf16_k<<<Msz, 256>>>(ga,      ah);   // q bf16
    l2norm_bf16_k<<<Msz, 256>>>(ga + PL, al);   // k bf16
    vtrans_k<<<dim3(Ssz/32, Bsz*Hn*2), btr>>>(ga + 2*PL, vb);

    // 6) attention (bf16 mma)
    attn2_k<<<dim3(Ssz/128, Bsz*Hn), 256, ATT_SMEM>>>(ah, al, vb, mask, gatt);

    // 7) out = attn_out @ wo + bo
    split_k<<<(Msz*Csz/4)/256, 256>>>(gatt, ah, al);
    split_trans_k<<<gtr, btr>>>(wo, wh, wl, Csz, Csz);
    gemm_bf16_k<0><<<ggemm, 256, GEMM_SMEM>>>(ah, al, wh, wl, bo, out, Msz, Csz, Csz);
}

// round 9
// speedup vs baseline: 3.4505x; 1.0833x over previous
#include <cuda_runtime.h>
#include <cuda_bf16.h>
#include <math.h>
#include <cstdint>

#define Bsz 4
#define Ssz 2048
#define Csz 1024
#define Hn  16
#define Dh  64
#define Msz (Bsz*Ssz)   // 8192

// Scratch
__device__ float g_f32[3][(size_t)Msz*Csz];                 // fp32 GEMM outputs
__device__ __nv_bfloat16 g_h[3][(size_t)Msz*Csz];           // bf16 hi planes
__device__ __nv_bfloat16 g_l[3][(size_t)Msz*Csz];           // bf16 lo planes
__device__ __nv_bfloat16 g_vb[(size_t)Msz*Csz];             // V^T per (b,h): [d][s]
__device__ __nv_bfloat16 g_wh[3][(size_t)Csz*Csz];
__device__ __nv_bfloat16 g_wl[3][(size_t)Csz*Csz];

// ---------------------------------------------------------------------------
// PTX helpers (arch-neutral: ldmatrix / mma.sync / cp.async)
// ---------------------------------------------------------------------------
__device__ __forceinline__ uint32_t smem_u32(const void* p) {
    uint32_t a;
    asm("{ .reg .u64 t; cvta.to.shared.u64 t, %1; cvt.u32.u64 %0, t; }" : "=r"(a) : "l"(p));
    return a;
}
__device__ __forceinline__ void cp16(uint32_t saddr, const void* g) {
    asm volatile("cp.async.cg.shared.global [%0], [%1], 16;" :: "r"(saddr), "l"(g));
}
__device__ __forceinline__ void cp4(uint32_t saddr, const void* g) {
    asm volatile("cp.async.ca.shared.global [%0], [%1], 4;" :: "r"(saddr), "l"(g));
}
#define CP_COMMIT() asm volatile("cp.async.commit_group;" ::: "memory")
#define CP_WAIT1()  asm volatile("cp.async.wait_group 1;" ::: "memory")
#define CP_WAIT0()  asm volatile("cp.async.wait_group 0;" ::: "memory")

#define LDSM4(r, addr)                                                          \
    asm volatile("ldmatrix.sync.aligned.m8n8.x4.shared.b16 {%0,%1,%2,%3}, [%4];" \
        : "=r"((r)[0]), "=r"((r)[1]), "=r"((r)[2]), "=r"((r)[3]) : "r"(addr))
#define LDSM2(r, addr)                                                          \
    asm volatile("ldmatrix.sync.aligned.m8n8.x2.shared.b16 {%0,%1}, [%2];"      \
        : "=r"((r)[0]), "=r"((r)[1]) : "r"(addr))

#define MMA16816(d, a, b)                                                       \
    asm volatile("mma.sync.aligned.m16n8k16.row.col.f32.bf16.bf16.f32 "         \
        "{%0,%1,%2,%3}, {%4,%5,%6,%7}, {%8,%9}, {%0,%1,%2,%3};"                 \
        : "+f"((d)[0]), "+f"((d)[1]), "+f"((d)[2]), "+f"((d)[3])                \
        : "r"((a)[0]), "r"((a)[1]), "r"((a)[2]), "r"((a)[3]),                   \
          "r"((b)[0]), "r"((b)[1]))

__device__ __forceinline__ uint32_t pack_bf16(float lo, float hi) {
    uint32_t r;
    asm("cvt.rn.bf16x2.f32 %0, %1, %2;" : "=r"(r) : "f"(hi), "f"(lo));
    return r;
}

// Swizzled smem offset for a [rows x 32] bf16 tile (64B rows): granule g 0..3
__device__ __forceinline__ uint32_t tswz(int r, int g) {
    return (uint32_t)(r * 64 + ((g ^ ((r >> 1) & 3)) & 3) * 16);
}
// Swizzled offset for 128B rows (64 bf16): granule g 0..7
__device__ __forceinline__ uint32_t tswz128(int r, int g) {
    return (uint32_t)(r * 128 + ((g ^ (r & 7)) & 7) * 16);
}

// ---------------------------------------------------------------------------
// Split fp32 -> (hi, lo) bf16
// ---------------------------------------------------------------------------
__global__ void split_k(const float* __restrict__ in,
                        __nv_bfloat16* __restrict__ hi, __nv_bfloat16* __restrict__ lo)
{
    const size_t i4 = (size_t)blockIdx.x * blockDim.x + threadIdx.x;
    float4 v = *(const float4*)(in + i4 * 4);
    const float* pv = &v.x;
    __nv_bfloat16 h[4], l[4];
#pragma unroll
    for (int t = 0; t < 4; t++) {
        h[t] = __float2bfloat16(pv[t]);
        l[t] = __float2bfloat16(pv[t] - __bfloat162float(h[t]));
    }
    *(__nv_bfloat162*)(hi + i4*4)     = __nv_bfloat162(h[0], h[1]);
    *(__nv_bfloat162*)(hi + i4*4 + 2) = __nv_bfloat162(h[2], h[3]);
    *(__nv_bfloat162*)(lo + i4*4)     = __nv_bfloat162(l[0], l[1]);
    *(__nv_bfloat162*)(lo + i4*4 + 2) = __nv_bfloat162(l[2], l[3]);
}

// ---------------------------------------------------------------------------
// Transpose+split: W[K,N] fp32 -> hi/lo [N,K] bf16.
// ---------------------------------------------------------------------------
__global__ void split_trans_k(const float* __restrict__ W,
                              __nv_bfloat16* __restrict__ hi, __nv_bfloat16* __restrict__ lo,
                              int K, int N)
{
    __shared__ float t[32][33];
    const int k0 = blockIdx.y * 32, n0 = blockIdx.x * 32;
    const int tx = threadIdx.x, ty = threadIdx.y;
#pragma unroll
    for (int r = 0; r < 4; r++)
        t[ty + r*8][tx] = W[(size_t)(k0 + ty + r*8) * N + n0 + tx];
    __syncthreads();
#pragma unroll
    for (int r = 0; r < 4; r++) {
        const int n = n0 + ty + r*8, k = k0 + tx;
        const float v = t[tx][ty + r*8];
        const __nv_bfloat16 h = __float2bfloat16(v);
        hi[(size_t)n * K + k] = h;
        lo[(size_t)n * K + k] = __float2bfloat16(v - __bfloat162float(h));
    }
}

// ---------------------------------------------------------------------------
// V transpose to bf16: in [B,S,C] fp32 -> vt[(bh*64 + d)*Ssz + s] bf16
// ---------------------------------------------------------------------------
__global__ void vtrans_k(const float* __restrict__ in, __nv_bfloat16* __restrict__ vt)
{
    __shared__ float t[32][33];
    const int z = blockIdx.y;
    const int dblk = z & 1, bh = z >> 1;
    const int b = bh >> 4, h = bh & 15;
    const int s0 = blockIdx.x * 32;
    const int tx = threadIdx.x, ty = threadIdx.y;
#pragma unroll
    for (int r = 0; r < 4; r++)
        t[ty + r*8][tx] = in[(size_t)(b*Ssz + s0 + ty + r*8) * Csz + h*Dh + dblk*32 + tx];
    __syncthreads();
#pragma unroll
    for (int r = 0; r < 4; r++) {
        const int d = dblk*32 + ty + r*8;
        vt[((size_t)bh * Dh + d) * Ssz + s0 + tx] = __float2bfloat16(t[tx][ty + r*8]);
    }
}

// ---------------------------------------------------------------------------
// Batched split-bf16 GEMM on mma.sync (z = blockIdx.z selects plane).
// C[M,N] = act(A @ B^T + bias); A (hi,lo) [M,K], B (hi,lo) [N,K].
// 128x128 tile, BK=32, 256 threads, 2-stage cp.async pipeline.
// ---------------------------------------------------------------------------
__device__ __forceinline__ void stage_load(
    const __nv_bfloat16* __restrict__ Ahi, const __nv_bfloat16* __restrict__ Alo,
    const __nv_bfloat16* __restrict__ Bhi, const __nv_bfloat16* __restrict__ Blo,
    int K, int m0, int n0, int k0, uint32_t sb)
{
    const int t = threadIdx.x;
    const int r = t >> 1;
    const int g0 = (t & 1) * 2;
    const size_t arow = (size_t)(m0 + r) * K + k0;
    const size_t brow = (size_t)(n0 + r) * K + k0;
#pragma unroll
    for (int gg = 0; gg < 2; gg++) {
        const int g = g0 + gg;
        const uint32_t so = tswz(r, g);
        cp16(sb + so,         Ahi + arow + g*8);
        cp16(sb + 8192 + so,  Alo + arow + g*8);
        cp16(sb + 16384 + so, Bhi + brow + g*8);
        cp16(sb + 24576 + so, Blo + brow + g*8);
    }
}

template<int ACT>
__global__ __launch_bounds__(256, 1) void gemm_bf16_k(
    const __nv_bfloat16* __restrict__ Ahi_, const __nv_bfloat16* __restrict__ Alo_,
    const __nv_bfloat16* __restrict__ Bhi_, const __nv_bfloat16* __restrict__ Blo_,
    const float* __restrict__ bias0, const float* __restrict__ bias1,
    const float* __restrict__ bias2,
    float* __restrict__ C_,
    int M, int N, int K, size_t strideA, size_t strideB, size_t strideC)
{
    extern __shared__ char sm_[];
    const uint32_t sbase = smem_u32(sm_);
    const int tid  = threadIdx.x;
    const int lane = tid & 31;
    const int warp = tid >> 5;
    const int wm = warp >> 2;
    const int wn = warp & 3;
    const int m0 = blockIdx.y * 128, n0 = blockIdx.x * 128;
    const int z  = blockIdx.z;

    const __nv_bfloat16* Ahi = Ahi_ + (size_t)z * strideA;
    const __nv_bfloat16* Alo = Alo_ + (size_t)z * strideA;
    const __nv_bfloat16* Bhi = Bhi_ + (size_t)z * strideB;
    const __nv_bfloat16* Blo = Blo_ + (size_t)z * strideB;
    const float* bias = (z == 0) ? bias0 : ((z == 1) ? bias1 : bias2);
    float* C = C_ + (size_t)z * strideC;

    float acc[4][4][4];
#pragma unroll
    for (int i = 0; i < 4; i++)
#pragma unroll
        for (int j = 0; j < 4; j++)
#pragma unroll
            for (int c = 0; c < 4; c++) acc[i][j][c] = 0.f;

    const int NIT = K >> 5;

    stage_load(Ahi, Alo, Bhi, Blo, K, m0, n0, 0, sbase);
    CP_COMMIT();

    for (int it = 0; it < NIT; it++) {
        if (it + 1 < NIT) {
            stage_load(Ahi, Alo, Bhi, Blo, K, m0, n0, (it+1) << 5,
                       sbase + ((it+1) & 1) * 32768);
            CP_COMMIT();
            CP_WAIT1();
        } else {
            CP_WAIT0();
        }
        __syncthreads();

        const uint32_t sb = sbase + (it & 1) * 32768;
        const int lr  = lane & 15;
        const int hf  = lane >> 4;
        const int lnb = lane & 7;
        const int hfb = (lane >> 3) & 1;

#pragma unroll
        for (int kk = 0; kk < 2; kk++) {
            uint32_t ah[4][4], al[4][4], bh[4][2], bl[4][2];
#pragma unroll
            for (int mt = 0; mt < 4; mt++) {
                const int r = wm*64 + mt*16 + lr;
                const uint32_t off = tswz(r, kk*2 + hf);
                LDSM4(ah[mt], sb + off);
                LDSM4(al[mt], sb + 8192 + off);
            }
#pragma unroll
            for (int nt = 0; nt < 4; nt++) {
                const int rn = wn*32 + nt*8 + lnb;
                const uint32_t off = tswz(rn, kk*2 + hfb);
                LDSM2(bh[nt], sb + 16384 + off);
                LDSM2(bl[nt], sb + 24576 + off);
            }
#pragma unroll
            for (int mt = 0; mt < 4; mt++)
#pragma unroll
                for (int nt = 0; nt < 4; nt++) {
                    MMA16816(acc[mt][nt], ah[mt], bh[nt]);
                    MMA16816(acc[mt][nt], ah[mt], bl[nt]);
                    MMA16816(acc[mt][nt], al[mt], bh[nt]);
                }
        }
        __syncthreads();
    }

    const int gid = lane >> 2;
    const int tg  = lane & 3;
#pragma unroll
    for (int mt = 0; mt < 4; mt++) {
#pragma unroll
        for (int nt = 0; nt < 4; nt++) {
            const int ncol = n0 + wn*32 + nt*8 + tg*2;
            const float b0 = __ldg(&bias[ncol]);
            const float b1 = __ldg(&bias[ncol + 1]);
#pragma unroll
            for (int h = 0; h < 2; h++) {
                const int row = m0 + wm*64 + mt*16 + gid + h*8;
                float v0 = acc[mt][nt][h*2 + 0] + b0;
                float v1 = acc[mt][nt][h*2 + 1] + b1;
                if (ACT) {
                    v0 = v0 / (1.f + __expf(-v0));
                    v1 = v1 / (1.f + __expf(-v1));
                }
                float2 o = make_float2(v0, v1);
                *(float2*)(C + (size_t)row * N + ncol) = o;
            }
        }
    }
}

// ---------------------------------------------------------------------------
// Fused depthwise conv k=3 + split to (hi,lo) bf16. Batched over z.
// ---------------------------------------------------------------------------
__global__ void dwconv_split_k(
    const float* __restrict__ in_, 
    const float* __restrict__ dw0, const float* __restrict__ dw1, const float* __restrict__ dw2,
    const float* __restrict__ db0, const float* __restrict__ db1, const float* __restrict__ db2,
    __nv_bfloat16* __restrict__ hi_, __nv_bfloat16* __restrict__ lo_)
{
    const int z = blockIdx.y;
    const float* in = in_ + (size_t)z * Msz * Csz;
    const float* dw  = (z == 0) ? dw0 : ((z == 1) ? dw1 : dw2);
    const float* dwb = (z == 0) ? db0 : ((z == 1) ? db1 : db2);
    __nv_bfloat16* hi = hi_ + (size_t)z * Msz * Csz;
    __nv_bfloat16* lo = lo_ + (size_t)z * Msz * Csz;

    const int idx = blockIdx.x * blockDim.x + threadIdx.x;
    const int c4 = (idx & (Csz/4 - 1)) * 4;
    const int m  = idx >> 8;
    const int s  = m & (Ssz - 1);

    float4 x0 = make_float4(0,0,0,0), x2 = make_float4(0,0,0,0);
    if (s > 0)        x0 = *(const float4*)(in + (size_t)(m-1)*Csz + c4);
    const float4 x1 =      *(const float4*)(in + (size_t)m*Csz + c4);
    if (s < Ssz - 1)  x2 = *(const float4*)(in + (size_t)(m+1)*Csz + c4);

    const float* p0 = &x0.x; const float* p1 = &x1.x; const float* p2 = &x2.x;
    __nv_bfloat16 h[4], l[4];
#pragma unroll
    for (int t = 0; t < 4; t++) {
        const int c = c4 + t;
        const float v = dwb[c] + dw[c*3+0]*p0[t] + dw[c*3+1]*p1[t] + dw[c*3+2]*p2[t];
        h[t] = __float2bfloat16(v);
        l[t] = __float2bfloat16(v - __bfloat162float(h[t]));
    }
    *(__nv_bfloat162*)(hi + (size_t)m*Csz + c4)     = __nv_bfloat162(h[0], h[1]);
    *(__nv_bfloat162*)(hi + (size_t)m*Csz + c4 + 2) = __nv_bfloat162(h[2], h[3]);
    *(__nv_bfloat162*)(lo + (size_t)m*Csz + c4)     = __nv_bfloat162(l[0], l[1]);
    *(__nv_bfloat162*)(lo + (size_t)m*Csz + c4 + 2) = __nv_bfloat162(l[2], l[3]);
}

// ---------------------------------------------------------------------------
// L2 normalize over C=1024, output bf16.
// ---------------------------------------------------------------------------
__global__ void l2norm_bf16_k(const float* __restrict__ src, __nv_bfloat16* __restrict__ dst)
{
    __shared__ float red[8];
    const float* p = src + (size_t)blockIdx.x * Csz;
    float4 v = *(const float4*)(p + threadIdx.x*4);
    float ss = v.x*v.x + v.y*v.y + v.z*v.z + v.w*v.w;
#pragma unroll
    for (int off = 16; off; off >>= 1) ss += __shfl_xor_sync(0xffffffffu, ss, off);
    if ((threadIdx.x & 31) == 0) red[threadIdx.x >> 5] = ss;
    __syncthreads();
    if (threadIdx.x == 0) {
        float t = 0.f;
#pragma unroll
        for (int i = 0; i < 8; i++) t += red[i];
        red[0] = t;
    }
    __syncthreads();
    const float inv = 1.0f / fmaxf(sqrtf(red[0]), 1e-12f);
    __nv_bfloat16* d = dst + (size_t)blockIdx.x * Csz + threadIdx.x*4;
    *(__nv_bfloat162*)(d)     = __nv_bfloat162(__float2bfloat16(v.x*inv), __float2bfloat16(v.y*inv));
    *(__nv_bfloat162*)(d + 2) = __nv_bfloat162(__float2bfloat16(v.z*inv), __float2bfloat16(v.w*inv));
}

// ---------------------------------------------------------------------------
// Flash attention on mma.sync (bf16 in, fp32 accum). Epilogue emits split
// (hi,lo) bf16 directly for the final GEMM.
// Block: 128 queries x (b,h). 8 warps. K/V chunks of 64, double-buffered.
// ---------------------------------------------------------------------------
#define ATT_STG 16640
__device__ __forceinline__ void attn_stage(
    const __nv_bfloat16* __restrict__ kb, const __nv_bfloat16* __restrict__ vt,
    const int* __restrict__ mask, size_t qkbase, size_t vbase, int b,
    int chunk, uint32_t st)
{
    const int tid = threadIdx.x;
#pragma unroll
    for (int i = 0; i < 2; i++) {
        const int idx = tid + i*256;
        const int r = idx >> 3, g = idx & 7;
        const uint32_t so = tswz128(r, g);
        cp16(st + so,        kb + qkbase + (size_t)(chunk*64 + r) * Csz + g*8);
        cp16(st + 8192 + so, vt + vbase + (size_t)r * Ssz + chunk*64 + g*8);
    }
    if (tid < 64)
        cp4(st + 16384 + tid*4, mask + (size_t)b * Ssz + chunk*64 + tid);
}

__global__ __launch_bounds__(256, 1) void attn2_k(
    const __nv_bfloat16* __restrict__ qb, const __nv_bfloat16* __restrict__ kb,
    const __nv_bfloat16* __restrict__ vt, const int* __restrict__ mask,
    __nv_bfloat16* __restrict__ oh, __nv_bfloat16* __restrict__ ol)
{
    extern __shared__ char sm_[];
    const uint32_t sbase = smem_u32(sm_);
    const int tid = threadIdx.x, lane = tid & 31, warp = tid >> 5;
    const int q0 = blockIdx.x * 128;
    const int bh = blockIdx.y;
    const int b = bh >> 4, h = bh & 15;

    const size_t qkbase = ((size_t)b * Ssz) * Csz + h * Dh;
    const size_t vbase  = (size_t)bh * Dh * Ssz;

    // Q -> smem (128 rows x 128B)
#pragma unroll
    for (int i = 0; i < 4; i++) {
        const int idx = tid + i*256;
        const int r = idx >> 3, g = idx & 7;
        cp16(sbase + tswz128(r, g), qb + qkbase + (size_t)(q0 + r) * Csz + g*8);
    }
    CP_COMMIT();

    const uint32_t kvb = sbase + 16384;
    attn_stage(kb, vt, mask, qkbase, vbase, b, 0, kvb);
    CP_COMMIT();

    float oacc[8][4];
#pragma unroll
    for (int nt = 0; nt < 8; nt++)
#pragma unroll
        for (int c = 0; c < 4; c++) oacc[nt][c] = 0.f;
    float m0 = -1e30f, m1 = -1e30f, l0 = 0.f, l1 = 0.f;
    uint32_t aq[4][4];

    const int cb = (lane & 3) * 2;

    for (int it = 0; it < Ssz/64; it++) {
        if (it + 1 < Ssz/64) {
            attn_stage(kb, vt, mask, qkbase, vbase, b, it+1, kvb + ((it+1)&1)*ATT_STG);
            CP_COMMIT();
            CP_WAIT1();
        } else {
            CP_WAIT0();
        }
        __syncthreads();

        if (it == 0) {
#pragma unroll
            for (int ks = 0; ks < 4; ks++) {
                const int r = warp*16 + (lane & 15);
                const int g = ks*2 + (lane >> 4);
                LDSM4(aq[ks], sbase + tswz128(r, g));
            }
        }

        const uint32_t st = kvb + (it & 1) * ATT_STG;
        const int* Ms = (const int*)(sm_ + 16384 + (it & 1) * ATT_STG + 16384);

        // S = Q K^T
        float sacc[8][4];
#pragma unroll
        for (int nt = 0; nt < 8; nt++)
#pragma unroll
            for (int c = 0; c < 4; c++) sacc[nt][c] = 0.f;

#pragma unroll
        for (int ks = 0; ks < 4; ks++) {
#pragma unroll
            for (int nt = 0; nt < 8; nt++) {
                uint32_t kf[2];
                const int r = nt*8 + (lane & 7);
                const int g = ks*2 + ((lane >> 3) & 1);
                LDSM2(kf, st + tswz128(r, g));
                MMA16816(sacc[nt], aq[ks], kf);
            }
        }

        // scale + mask + online softmax
        float mx0 = -1e30f, mx1 = -1e30f;
#pragma unroll
        for (int nt = 0; nt < 8; nt++) {
            const int c = nt*8 + cb;
            const bool k0m = Ms[c] != 0, k1m = Ms[c+1] != 0;
            sacc[nt][0] = k0m ? sacc[nt][0]*0.125f : -1e30f;
            sacc[nt][1] = k1m ? sacc[nt][1]*0.125f : -1e30f;
            sacc[nt][2] = k0m ? sacc[nt][2]*0.125f : -1e30f;
            sacc[nt][3] = k1m ? sacc[nt][3]*0.125f : -1e30f;
            mx0 = fmaxf(mx0, fmaxf(sacc[nt][0], sacc[nt][1]));
            mx1 = fmaxf(mx1, fmaxf(sacc[nt][2], sacc[nt][3]));
        }
        mx0 = fmaxf(mx0, __shfl_xor_sync(0xffffffffu, mx0, 1));
        mx0 = fmaxf(mx0, __shfl_xor_sync(0xffffffffu, mx0, 2));
        mx1 = fmaxf(mx1, __shfl_xor_sync(0xffffffffu, mx1, 1));
        mx1 = fmaxf(mx1, __shfl_xor_sync(0xffffffffu, mx1, 2));
        const float mn0 = fmaxf(m0, mx0), mn1 = fmaxf(m1, mx1);
        const float c0 = __expf(m0 - mn0), c1 = __expf(m1 - mn1);
        m0 = mn0; m1 = mn1;
        float rs0 = 0.f, rs1 = 0.f;
#pragma unroll
        for (int nt = 0; nt < 8; nt++) {
            sacc[nt][0] = __expf(sacc[nt][0] - mn0);
            sacc[nt][1] = __expf(sacc[nt][1] - mn0);
            sacc[nt][2] = __expf(sacc[nt][2] - mn1);
            sacc[nt][3] = __expf(sacc[nt][3] - mn1);
            rs0 += sacc[nt][0] + sacc[nt][1];
            rs1 += sacc[nt][2] + sacc[nt][3];
        }
        rs0 += __shfl_xor_sync(0xffffffffu, rs0, 1);
        rs0 += __shfl_xor_sync(0xffffffffu, rs0, 2);
        rs1 += __shfl_xor_sync(0xffffffffu, rs1, 1);
        rs1 += __shfl_xor_sync(0xffffffffu, rs1, 2);
        l0 = l0*c0 + rs0;
        l1 = l1*c1 + rs1;
#pragma unroll
        for (int nt = 0; nt < 8; nt++) {
            oacc[nt][0] *= c0; oacc[nt][1] *= c0;
            oacc[nt][2] *= c1; oacc[nt][3] *= c1;
        }

        // O += P V
#pragma unroll
        for (int ks = 0; ks < 4; ks++) {
            uint32_t pa[4];
            pa[0] = pack_bf16(sacc[2*ks][0],   sacc[2*ks][1]);
            pa[1] = pack_bf16(sacc[2*ks][2],   sacc[2*ks][3]);
            pa[2] = pack_bf16(sacc[2*ks+1][0], sacc[2*ks+1][1]);
            pa[3] = pack_bf16(sacc[2*ks+1][2], sacc[2*ks+1][3]);
#pragma unroll
            for (int nt = 0; nt < 8; nt++) {
                uint32_t vf[2];
                const int r = nt*8 + (lane & 7);
                const int g = ks*2 + ((lane >> 3) & 1);
                LDSM2(vf, st + 8192 + tswz128(r, g));
                MMA16816(oacc[nt], pa, vf);
            }
        }
        __syncthreads();
    }

    // Epilogue: normalize and emit split (hi, lo) bf16
    const float inv0 = 1.f / l0, inv1 = 1.f / l1;
    const int r0 = q0 + warp*16 + (lane >> 2);
#pragma unroll
    for (int nt = 0; nt < 8; nt++) {
        const int c = h*Dh + nt*8 + cb;
#pragma unroll
        for (int hh = 0; hh < 2; hh++) {
            const float inv = hh ? inv1 : inv0;
            const float v0 = oacc[nt][hh*2 + 0] * inv;
            const float v1 = oacc[nt][hh*2 + 1] * inv;
            const __nv_bfloat16 h0 = __float2bfloat16(v0);
            const __nv_bfloat16 h1 = __float2bfloat16(v1);
            const size_t off = ((size_t)b*Ssz + r0 + hh*8) * Csz + c;
            *(__nv_bfloat162*)(oh + off) = __nv_bfloat162(h0, h1);
            *(__nv_bfloat162*)(ol + off) = __nv_bfloat162(
                __float2bfloat16(v0 - __bfloat162float(h0)),
                __float2bfloat16(v1 - __bfloat162float(h1)));
        }
    }
}

// ---------------------------------------------------------------------------
extern "C" void kernel_launch(void* const* d_in, const int* in_sizes, int n_in,
                              void* d_out, int out_size)
{
    const float* x    = (const float*)d_in[0];
    const int*   mask = (const int*)  d_in[1];
    const float* W[3]   = {(const float*)d_in[2],  (const float*)d_in[8],  (const float*)d_in[14]};
    const float* Bi[3]  = {(const float*)d_in[3],  (const float*)d_in[9],  (const float*)d_in[15]};
    const float* DW[3]  = {(const float*)d_in[4],  (const float*)d_in[10], (const float*)d_in[16]};
    const float* DWB[3] = {(const float*)d_in[5],  (const float*)d_in[11], (const float*)d_in[17]};
    const float* PW[3]  = {(const float*)d_in[6],  (const float*)d_in[12], (const float*)d_in[18]};
    const float* PWB[3] = {(const float*)d_in[7],  (const float*)d_in[13], (const float*)d_in[19]};
    const float* wo = (const float*)d_in[20];
    const float* bo = (const float*)d_in[21];
    float* out = (float*)d_out;

    float *gf;
    __nv_bfloat16 *gh, *gl, *vb, *wh, *wl;
    cudaGetSymbolAddress((void**)&gf, g_f32);
    cudaGetSymbolAddress((void**)&gh, g_h);
    cudaGetSymbolAddress((void**)&gl, g_l);
    cudaGetSymbolAddress((void**)&vb, g_vb);
    cudaGetSymbolAddress((void**)&wh, g_wh);
    cudaGetSymbolAddress((void**)&wl, g_wl);
    const size_t PL = (size_t)Msz * Csz;
    const size_t WL = (size_t)Csz * Csz;

    const int GEMM_SMEM = 65536;
    const int ATT_SMEM  = 16384 + 2*ATT_STG;   // 49664
    cudaFuncSetAttribute(gemm_bf16_k<0>, cudaFuncAttributeMaxDynamicSharedMemorySize, GEMM_SMEM);
    cudaFuncSetAttribute(gemm_bf16_k<1>, cudaFuncAttributeMaxDynamicSharedMemorySize, GEMM_SMEM);
    cudaFuncSetAttribute(attn2_k, cudaFuncAttributeMaxDynamicSharedMemorySize, ATT_SMEM);

    const dim3 ggemm1(Csz/128, Msz/128, 1);
    const dim3 ggemm3(Csz/128, Msz/128, 3);
    const dim3 gtr(Csz/32, Csz/32), btr(32, 8);

    // 1) split x -> (gh0, gl0)
    split_k<<<(Msz*Csz/4)/256, 256>>>(x, gh, gl);

    // 2) weight prep for QKV
    for (int p = 0; p < 3; p++)
        split_trans_k<<<gtr, btr>>>(W[p], wh + p*WL, wl + p*WL, Csz, Csz);

    // 3) batched QKV GEMM: q/k/v = silu(x @ W + b) -> gf[z]
    gemm_bf16_k<1><<<ggemm3, 256, GEMM_SMEM>>>(
        gh, gl, wh, wl, Bi[0], Bi[1], Bi[2], gf,
        Msz, Csz, Csz, 0, WL, PL);

    // 4) fused depthwise conv + split: gf[z] -> (gh[z], gl[z])
    dwconv_split_k<<<dim3((Msz*Csz/4)/256, 3), 256>>>(
        gf, DW[0], DW[1], DW[2], DWB[0], DWB[1], DWB[2], gh, gl);

    // 5) weight prep for pointwise (PW already [N,K])
    for (int p = 0; p < 3; p++)
        split_k<<<(Csz*Csz/4)/256, 256>>>(PW[p], wh + p*WL, wl + p*WL);

    // 6) batched pointwise GEMM -> gf[z]
    gemm_bf16_k<0><<<ggemm3, 256, GEMM_SMEM>>>(
        gh, gl, wh, wl, PWB[0], PWB[1], PWB[2], gf,
        Msz, Csz, Csz, PL, WL, PL);

    // 7) l2norm q,k -> bf16 (gh0 = q, gh1 = k); V -> bf16 transposed
    l2norm_bf16_k<<<Msz, 256>>>(gf,      gh);
    l2norm_bf16_k<<<Msz, 256>>>(gf + PL, gh + PL);
    vtrans_k<<<dim3(Ssz/32, Bsz*Hn*2), btr>>>(gf + 2*PL, vb);

    // 8) weight prep for out-proj
    split_trans_k<<<gtr, btr>>>(wo, wh, wl, Csz, Csz);

    // 9) attention -> split output (gl0 = hi, gl1 = lo)
    attn2_k<<<dim3(Ssz/128, Bsz*Hn), 256, ATT_SMEM>>>(
        gh, gh + PL, vb, mask, gl, gl + PL);

    // 10) out = attn_out @ wo + bo
    gemm_bf16_k<0><<<ggemm1, 256, GEMM_SMEM>>>(
        gl, gl + PL, wh, wl, bo, bo, bo, out,
        Msz, Csz, Csz, 0, 0, 0);
}

// round 10
// speedup vs baseline: 4.3197x; 1.2519x over previous
#include <cuda_runtime.h>
#include <cuda_fp16.h>
#include <math.h>
#include <cstdint>

#define Bsz 4
#define Ssz 2048
#define Csz 1024
#define Hn  16
#define Dh  64
#define Msz (Bsz*Ssz)   // 8192

// Scratch
__device__ float  g_f32[3][(size_t)Msz*Csz];      // fp32 GEMM outputs
__device__ __half g_h[3][(size_t)Msz*Csz];        // fp16 activation planes
__device__ __half g_o[(size_t)Msz*Csz];           // fp16 attention output
__device__ __half g_vb[(size_t)Msz*Csz];          // V^T per (b,h): [d][s]
__device__ __half g_wh[3][(size_t)Csz*Csz];       // weight hi
__device__ __half g_wl[3][(size_t)Csz*Csz];       // weight lo

// ---------------------------------------------------------------------------
// PTX helpers (arch-neutral: ldmatrix / mma.sync / cp.async)
// ---------------------------------------------------------------------------
__device__ __forceinline__ uint32_t smem_u32(const void* p) {
    uint32_t a;
    asm("{ .reg .u64 t; cvta.to.shared.u64 t, %1; cvt.u32.u64 %0, t; }" : "=r"(a) : "l"(p));
    return a;
}
__device__ __forceinline__ void cp16(uint32_t saddr, const void* g) {
    asm volatile("cp.async.cg.shared.global [%0], [%1], 16;" :: "r"(saddr), "l"(g));
}
__device__ __forceinline__ void cp4(uint32_t saddr, const void* g) {
    asm volatile("cp.async.ca.shared.global [%0], [%1], 4;" :: "r"(saddr), "l"(g));
}
#define CP_COMMIT() asm volatile("cp.async.commit_group;" ::: "memory")
#define CP_WAIT1()  asm volatile("cp.async.wait_group 1;" ::: "memory")
#define CP_WAIT0()  asm volatile("cp.async.wait_group 0;" ::: "memory")

#define LDSM4(r, addr)                                                          \
    asm volatile("ldmatrix.sync.aligned.m8n8.x4.shared.b16 {%0,%1,%2,%3}, [%4];" \
        : "=r"((r)[0]), "=r"((r)[1]), "=r"((r)[2]), "=r"((r)[3]) : "r"(addr))
#define LDSM2(r, addr)                                                          \
    asm volatile("ldmatrix.sync.aligned.m8n8.x2.shared.b16 {%0,%1}, [%2];"      \
        : "=r"((r)[0]), "=r"((r)[1]) : "r"(addr))

#define MMA16816(d, a, b)                                                       \
    asm volatile("mma.sync.aligned.m16n8k16.row.col.f32.f16.f16.f32 "           \
        "{%0,%1,%2,%3}, {%4,%5,%6,%7}, {%8,%9}, {%0,%1,%2,%3};"                 \
        : "+f"((d)[0]), "+f"((d)[1]), "+f"((d)[2]), "+f"((d)[3])                \
        : "r"((a)[0]), "r"((a)[1]), "r"((a)[2]), "r"((a)[3]),                   \
          "r"((b)[0]), "r"((b)[1]))

__device__ __forceinline__ uint32_t pack_f16(float lo, float hi) {
    uint32_t r;
    asm("cvt.rn.f16x2.f32 %0, %1, %2;" : "=r"(r) : "f"(hi), "f"(lo));
    return r;
}

// Swizzled smem offset for a [rows x 32] f16 tile (64B rows): granule g 0..3
__device__ __forceinline__ uint32_t tswz(int r, int g) {
    return (uint32_t)(r * 64 + ((g ^ ((r >> 1) & 3)) & 3) * 16);
}
// Swizzled offset for 128B rows (64 f16): granule g 0..7
__device__ __forceinline__ uint32_t tswz128(int r, int g) {
    return (uint32_t)(r * 128 + ((g ^ (r & 7)) & 7) * 16);
}

// ---------------------------------------------------------------------------
// Convert fp32 -> fp16 (plain)
// ---------------------------------------------------------------------------
__global__ void cvt_f16_k(const float* __restrict__ in, __half* __restrict__ out)
{
    const size_t i4 = (size_t)blockIdx.x * blockDim.x + threadIdx.x;
    float4 v = *(const float4*)(in + i4 * 4);
    *(__half2*)(out + i4*4)     = __floats2half2_rn(v.x, v.y);
    *(__half2*)(out + i4*4 + 2) = __floats2half2_rn(v.z, v.w);
}

// ---------------------------------------------------------------------------
// Split fp32 -> (hi, lo) fp16 (for weights already [N,K])
// ---------------------------------------------------------------------------
__global__ void split_k(const float* __restrict__ in,
                        __half* __restrict__ hi, __half* __restrict__ lo)
{
    const size_t i4 = (size_t)blockIdx.x * blockDim.x + threadIdx.x;
    float4 v = *(const float4*)(in + i4 * 4);
    const float* pv = &v.x;
    __half h[4], l[4];
#pragma unroll
    for (int t = 0; t < 4; t++) {
        h[t] = __float2half_rn(pv[t]);
        l[t] = __float2half_rn(pv[t] - __half2float(h[t]));
    }
    *(__half2*)(hi + i4*4)     = __halves2half2(h[0], h[1]);
    *(__half2*)(hi + i4*4 + 2) = __halves2half2(h[2], h[3]);
    *(__half2*)(lo + i4*4)     = __halves2half2(l[0], l[1]);
    *(__half2*)(lo + i4*4 + 2) = __halves2half2(l[2], l[3]);
}

// ---------------------------------------------------------------------------
// Transpose+split: W[K,N] fp32 -> hi/lo [N,K] fp16.
// ---------------------------------------------------------------------------
__global__ void split_trans_k(const float* __restrict__ W,
                              __half* __restrict__ hi, __half* __restrict__ lo,
                              int K, int N)
{
    __shared__ float t[32][33];
    const int k0 = blockIdx.y * 32, n0 = blockIdx.x * 32;
    const int tx = threadIdx.x, ty = threadIdx.y;
#pragma unroll
    for (int r = 0; r < 4; r++)
        t[ty + r*8][tx] = W[(size_t)(k0 + ty + r*8) * N + n0 + tx];
    __syncthreads();
#pragma unroll
    for (int r = 0; r < 4; r++) {
        const int n = n0 + ty + r*8, k = k0 + tx;
        const float v = t[tx][ty + r*8];
        const __half h = __float2half_rn(v);
        hi[(size_t)n * K + k] = h;
        lo[(size_t)n * K + k] = __float2half_rn(v - __half2float(h));
    }
}

// ---------------------------------------------------------------------------
// V transpose to fp16: in [B,S,C] fp32 -> vt[(bh*64 + d)*Ssz + s]
// ---------------------------------------------------------------------------
__global__ void vtrans_k(const float* __restrict__ in, __half* __restrict__ vt)
{
    __shared__ float t[32][33];
    const int z = blockIdx.y;
    const int dblk = z & 1, bh = z >> 1;
    const int b = bh >> 4, h = bh & 15;
    const int s0 = blockIdx.x * 32;
    const int tx = threadIdx.x, ty = threadIdx.y;
#pragma unroll
    for (int r = 0; r < 4; r++)
        t[ty + r*8][tx] = in[(size_t)(b*Ssz + s0 + ty + r*8) * Csz + h*Dh + dblk*32 + tx];
    __syncthreads();
#pragma unroll
    for (int r = 0; r < 4; r++) {
        const int d = dblk*32 + ty + r*8;
        vt[((size_t)bh * Dh + d) * Ssz + s0 + tx] = __float2half_rn(t[tx][ty + r*8]);
    }
}

// ---------------------------------------------------------------------------
// 2-term fp16 GEMM on mma.sync, batched over blockIdx.z.
// C[M,N] = act(A @ (Bhi + Blo)^T + bias); A plain fp16 [M,K], B split [N,K].
// 128x128 tile, BK=32, 256 threads, 2-stage cp.async pipeline.
// Stage layout (24KB): A | Bhi | Blo @ 8KB each.
// ---------------------------------------------------------------------------
#define G_STG 24576
__device__ __forceinline__ void stage_load(
    const __half* __restrict__ A, const __half* __restrict__ Bh,
    const __half* __restrict__ Bl,
    int K, int m0, int n0, int k0, uint32_t sb)
{
    const int t = threadIdx.x;
    const int r = t >> 1;
    const int g0 = (t & 1) * 2;
    const size_t arow = (size_t)(m0 + r) * K + k0;
    const size_t brow = (size_t)(n0 + r) * K + k0;
#pragma unroll
    for (int gg = 0; gg < 2; gg++) {
        const int g = g0 + gg;
        const uint32_t so = tswz(r, g);
        cp16(sb + so,          A  + arow + g*8);
        cp16(sb + 8192 + so,   Bh + brow + g*8);
        cp16(sb + 16384 + so,  Bl + brow + g*8);
    }
}

template<int ACT>
__global__ __launch_bounds__(256, 1) void gemm_f16_k(
    const __half* __restrict__ A_,
    const __half* __restrict__ Bhi_, const __half* __restrict__ Blo_,
    const float* __restrict__ bias0, const float* __restrict__ bias1,
    const float* __restrict__ bias2,
    float* __restrict__ C_,
    int M, int N, int K, size_t strideA, size_t strideB, size_t strideC)
{
    extern __shared__ char sm_[];
    const uint32_t sbase = smem_u32(sm_);
    const int tid  = threadIdx.x;
    const int lane = tid & 31;
    const int warp = tid >> 5;
    const int wm = warp >> 2;
    const int wn = warp & 3;
    const int m0 = blockIdx.y * 128, n0 = blockIdx.x * 128;
    const int z  = blockIdx.z;

    const __half* A   = A_   + (size_t)z * strideA;
    const __half* Bhi = Bhi_ + (size_t)z * strideB;
    const __half* Blo = Blo_ + (size_t)z * strideB;
    const float* bias = (z == 0) ? bias0 : ((z == 1) ? bias1 : bias2);
    float* C = C_ + (size_t)z * strideC;

    float acc[4][4][4];
#pragma unroll
    for (int i = 0; i < 4; i++)
#pragma unroll
        for (int j = 0; j < 4; j++)
#pragma unroll
            for (int c = 0; c < 4; c++) acc[i][j][c] = 0.f;

    const int NIT = K >> 5;

    stage_load(A, Bhi, Blo, K, m0, n0, 0, sbase);
    CP_COMMIT();

    for (int it = 0; it < NIT; it++) {
        if (it + 1 < NIT) {
            stage_load(A, Bhi, Blo, K, m0, n0, (it+1) << 5,
                       sbase + ((it+1) & 1) * G_STG);
            CP_COMMIT();
            CP_WAIT1();
        } else {
            CP_WAIT0();
        }
        __syncthreads();

        const uint32_t sb = sbase + (it & 1) * G_STG;
        const int lr  = lane & 15;
        const int hf  = lane >> 4;
        const int lnb = lane & 7;
        const int hfb = (lane >> 3) & 1;

#pragma unroll
        for (int kk = 0; kk < 2; kk++) {
            uint32_t ah[4][4], bh[4][2], bl[4][2];
#pragma unroll
            for (int mt = 0; mt < 4; mt++) {
                const int r = wm*64 + mt*16 + lr;
                LDSM4(ah[mt], sb + tswz(r, kk*2 + hf));
            }
#pragma unroll
            for (int nt = 0; nt < 4; nt++) {
                const int rn = wn*32 + nt*8 + lnb;
                const uint32_t off = tswz(rn, kk*2 + hfb);
                LDSM2(bh[nt], sb + 8192 + off);
                LDSM2(bl[nt], sb + 16384 + off);
            }
#pragma unroll
            for (int mt = 0; mt < 4; mt++)
#pragma unroll
                for (int nt = 0; nt < 4; nt++) {
                    MMA16816(acc[mt][nt], ah[mt], bh[nt]);
                    MMA16816(acc[mt][nt], ah[mt], bl[nt]);
                }
        }
        __syncthreads();
    }

    const int gid = lane >> 2;
    const int tg  = lane & 3;
#pragma unroll
    for (int mt = 0; mt < 4; mt++) {
#pragma unroll
        for (int nt = 0; nt < 4; nt++) {
            const int ncol = n0 + wn*32 + nt*8 + tg*2;
            const float b0 = __ldg(&bias[ncol]);
            const float b1 = __ldg(&bias[ncol + 1]);
#pragma unroll
            for (int h = 0; h < 2; h++) {
                const int row = m0 + wm*64 + mt*16 + gid + h*8;
                float v0 = acc[mt][nt][h*2 + 0] + b0;
                float v1 = acc[mt][nt][h*2 + 1] + b1;
                if (ACT) {
                    v0 = v0 / (1.f + __expf(-v0));
                    v1 = v1 / (1.f + __expf(-v1));
                }
                float2 o = make_float2(v0, v1);
                *(float2*)(C + (size_t)row * N + ncol) = o;
            }
        }
    }
}

// ---------------------------------------------------------------------------
// Fused depthwise conv k=3 + convert to fp16. Batched over z.
// ---------------------------------------------------------------------------
__global__ void dwconv_f16_k(
    const float* __restrict__ in_,
    const float* __restrict__ dw0, const float* __restrict__ dw1, const float* __restrict__ dw2,
    const float* __restrict__ db0, const float* __restrict__ db1, const float* __restrict__ db2,
    __half* __restrict__ out_)
{
    const int z = blockIdx.y;
    const float* in = in_ + (size_t)z * Msz * Csz;
    const float* dw  = (z == 0) ? dw0 : ((z == 1) ? dw1 : dw2);
    const float* dwb = (z == 0) ? db0 : ((z == 1) ? db1 : db2);
    __half* out = out_ + (size_t)z * Msz * Csz;

    const int idx = blockIdx.x * blockDim.x + threadIdx.x;
    const int c4 = (idx & (Csz/4 - 1)) * 4;
    const int m  = idx >> 8;
    const int s  = m & (Ssz - 1);

    float4 x0 = make_float4(0,0,0,0), x2 = make_float4(0,0,0,0);
    if (s > 0)        x0 = *(const float4*)(in + (size_t)(m-1)*Csz + c4);
    const float4 x1 =      *(const float4*)(in + (size_t)m*Csz + c4);
    if (s < Ssz - 1)  x2 = *(const float4*)(in + (size_t)(m+1)*Csz + c4);

    const float* p0 = &x0.x; const float* p1 = &x1.x; const float* p2 = &x2.x;
    float v[4];
#pragma unroll
    for (int t = 0; t < 4; t++) {
        const int c = c4 + t;
        v[t] = dwb[c] + dw[c*3+0]*p0[t] + dw[c*3+1]*p1[t] + dw[c*3+2]*p2[t];
    }
    *(__half2*)(out + (size_t)m*Csz + c4)     = __floats2half2_rn(v[0], v[1]);
    *(__half2*)(out + (size_t)m*Csz + c4 + 2) = __floats2half2_rn(v[2], v[3]);
}

// ---------------------------------------------------------------------------
// L2 normalize over C=1024, output fp16.
// ---------------------------------------------------------------------------
__global__ void l2norm_f16_k(const float* __restrict__ src, __half* __restrict__ dst)
{
    __shared__ float red[8];
    const float* p = src + (size_t)blockIdx.x * Csz;
    float4 v = *(const float4*)(p + threadIdx.x*4);
    float ss = v.x*v.x + v.y*v.y + v.z*v.z + v.w*v.w;
#pragma unroll
    for (int off = 16; off; off >>= 1) ss += __shfl_xor_sync(0xffffffffu, ss, off);
    if ((threadIdx.x & 31) == 0) red[threadIdx.x >> 5] = ss;
    __syncthreads();
    if (threadIdx.x == 0) {
        float t = 0.f;
#pragma unroll
        for (int i = 0; i < 8; i++) t += red[i];
        red[0] = t;
    }
    __syncthreads();
    const float inv = 1.0f / fmaxf(sqrtf(red[0]), 1e-12f);
    __half* d = dst + (size_t)blockIdx.x * Csz + threadIdx.x*4;
    *(__half2*)(d)     = __floats2half2_rn(v.x*inv, v.y*inv);
    *(__half2*)(d + 2) = __floats2half2_rn(v.z*inv, v.w*inv);
}

// ---------------------------------------------------------------------------
// Flash attention on mma.sync (fp16 in, fp32 accum). Output plain fp16.
// Block: 128 queries x (b,h). 8 warps. K/V chunks of 64, double-buffered.
// Stage = K(8KB) + V^T(8KB) + mask(256B) = 16640B.
// ---------------------------------------------------------------------------
#define ATT_STG 16640
__device__ __forceinline__ void attn_stage(
    const __half* __restrict__ kb, const __half* __restrict__ vt,
    const int* __restrict__ mask, size_t qkbase, size_t vbase, int b,
    int chunk, uint32_t st)
{
    const int tid = threadIdx.x;
#pragma unroll
    for (int i = 0; i < 2; i++) {
        const int idx = tid + i*256;
        const int r = idx >> 3, g = idx & 7;
        const uint32_t so = tswz128(r, g);
        cp16(st + so,        kb + qkbase + (size_t)(chunk*64 + r) * Csz + g*8);
        cp16(st + 8192 + so, vt + vbase + (size_t)r * Ssz + chunk*64 + g*8);
    }
    if (tid < 64)
        cp4(st + 16384 + tid*4, mask + (size_t)b * Ssz + chunk*64 + tid);
}

__global__ __launch_bounds__(256, 1) void attn2_k(
    const __half* __restrict__ qb, const __half* __restrict__ kb,
    const __half* __restrict__ vt, const int* __restrict__ mask,
    __half* __restrict__ og)
{
    extern __shared__ char sm_[];
    const uint32_t sbase = smem_u32(sm_);
    const int tid = threadIdx.x, lane = tid & 31, warp = tid >> 5;
    const int q0 = blockIdx.x * 128;
    const int bh = blockIdx.y;
    const int b = bh >> 4, h = bh & 15;

    const size_t qkbase = ((size_t)b * Ssz) * Csz + h * Dh;
    const size_t vbase  = (size_t)bh * Dh * Ssz;

    // Q -> smem (128 rows x 128B)
#pragma unroll
    for (int i = 0; i < 4; i++) {
        const int idx = tid + i*256;
        const int r = idx >> 3, g = idx & 7;
        cp16(sbase + tswz128(r, g), qb + qkbase + (size_t)(q0 + r) * Csz + g*8);
    }
    CP_COMMIT();

    const uint32_t kvb = sbase + 16384;
    attn_stage(kb, vt, mask, qkbase, vbase, b, 0, kvb);
    CP_COMMIT();

    float oacc[8][4];
#pragma unroll
    for (int nt = 0; nt < 8; nt++)
#pragma unroll
        for (int c = 0; c < 4; c++) oacc[nt][c] = 0.f;
    float m0 = -1e30f, m1 = -1e30f, l0 = 0.f, l1 = 0.f;
    uint32_t aq[4][4];

    const int cb = (lane & 3) * 2;

    for (int it = 0; it < Ssz/64; it++) {
        if (it + 1 < Ssz/64) {
            attn_stage(kb, vt, mask, qkbase, vbase, b, it+1, kvb + ((it+1)&1)*ATT_STG);
            CP_COMMIT();
            CP_WAIT1();
        } else {
            CP_WAIT0();
        }
        __syncthreads();

        if (it == 0) {
#pragma unroll
            for (int ks = 0; ks < 4; ks++) {
                const int r = warp*16 + (lane & 15);
                const int g = ks*2 + (lane >> 4);
                LDSM4(aq[ks], sbase + tswz128(r, g));
            }
        }

        const uint32_t st = kvb + (it & 1) * ATT_STG;
        const int* Ms = (const int*)(sm_ + 16384 + (it & 1) * ATT_STG + 16384);

        // S = Q K^T
        float sacc[8][4];
#pragma unroll
        for (int nt = 0; nt < 8; nt++)
#pragma unroll
            for (int c = 0; c < 4; c++) sacc[nt][c] = 0.f;

#pragma unroll
        for (int ks = 0; ks < 4; ks++) {
#pragma unroll
            for (int nt = 0; nt < 8; nt++) {
                uint32_t kf[2];
                const int r = nt*8 + (lane & 7);
                const int g = ks*2 + ((lane >> 3) & 1);
                LDSM2(kf, st + tswz128(r, g));
                MMA16816(sacc[nt], aq[ks], kf);
            }
        }

        // scale + mask + online softmax
        float mx0 = -1e30f, mx1 = -1e30f;
#pragma unroll
        for (int nt = 0; nt < 8; nt++) {
            const int c = nt*8 + cb;
            const bool k0m = Ms[c] != 0, k1m = Ms[c+1] != 0;
            sacc[nt][0] = k0m ? sacc[nt][0]*0.125f : -1e30f;
            sacc[nt][1] = k1m ? sacc[nt][1]*0.125f : -1e30f;
            sacc[nt][2] = k0m ? sacc[nt][2]*0.125f : -1e30f;
            sacc[nt][3] = k1m ? sacc[nt][3]*0.125f : -1e30f;
            mx0 = fmaxf(mx0, fmaxf(sacc[nt][0], sacc[nt][1]));
            mx1 = fmaxf(mx1, fmaxf(sacc[nt][2], sacc[nt][3]));
        }
        mx0 = fmaxf(mx0, __shfl_xor_sync(0xffffffffu, mx0, 1));
        mx0 = fmaxf(mx0, __shfl_xor_sync(0xffffffffu, mx0, 2));
        mx1 = fmaxf(mx1, __shfl_xor_sync(0xffffffffu, mx1, 1));
        mx1 = fmaxf(mx1, __shfl_xor_sync(0xffffffffu, mx1, 2));
        const float mn0 = fmaxf(m0, mx0), mn1 = fmaxf(m1, mx1);
        const float c0 = __expf(m0 - mn0), c1 = __expf(m1 - mn1);
        m0 = mn0; m1 = mn1;
        float rs0 = 0.f, rs1 = 0.f;
#pragma unroll
        for (int nt = 0; nt < 8; nt++) {
            sacc[nt][0] = __expf(sacc[nt][0] - mn0);
            sacc[nt][1] = __expf(sacc[nt][1] - mn0);
            sacc[nt][2] = __expf(sacc[nt][2] - mn1);
            sacc[nt][3] = __expf(sacc[nt][3] - mn1);
            rs0 += sacc[nt][0] + sacc[nt][1];
            rs1 += sacc[nt][2] + sacc[nt][3];
        }
        rs0 += __shfl_xor_sync(0xffffffffu, rs0, 1);
        rs0 += __shfl_xor_sync(0xffffffffu, rs0, 2);
        rs1 += __shfl_xor_sync(0xffffffffu, rs1, 1);
        rs1 += __shfl_xor_sync(0xffffffffu, rs1, 2);
        l0 = l0*c0 + rs0;
        l1 = l1*c1 + rs1;
#pragma unroll
        for (int nt = 0; nt < 8; nt++) {
            oacc[nt][0] *= c0; oacc[nt][1] *= c0;
            oacc[nt][2] *= c1; oacc[nt][3] *= c1;
        }

        // O += P V
#pragma unroll
        for (int ks = 0; ks < 4; ks++) {
            uint32_t pa[4];
            pa[0] = pack_f16(sacc[2*ks][0],   sacc[2*ks][1]);
            pa[1] = pack_f16(sacc[2*ks][2],   sacc[2*ks][3]);
            pa[2] = pack_f16(sacc[2*ks+1][0], sacc[2*ks+1][1]);
            pa[3] = pack_f16(sacc[2*ks+1][2], sacc[2*ks+1][3]);
#pragma unroll
            for (int nt = 0; nt < 8; nt++) {
                uint32_t vf[2];
                const int r = nt*8 + (lane & 7);
                const int g = ks*2 + ((lane >> 3) & 1);
                LDSM2(vf, st + 8192 + tswz128(r, g));
                MMA16816(oacc[nt], pa, vf);
            }
        }
        __syncthreads();
    }

    // Epilogue: normalize and emit plain fp16
    const float inv0 = 1.f / l0, inv1 = 1.f / l1;
    const int r0 = q0 + warp*16 + (lane >> 2);
#pragma unroll
    for (int nt = 0; nt < 8; nt++) {
        const int c = h*Dh + nt*8 + cb;
        *(__half2*)(og + ((size_t)b*Ssz + r0) * Csz + c) =
            __floats2half2_rn(oacc[nt][0]*inv0, oacc[nt][1]*inv0);
        *(__half2*)(og + ((size_t)b*Ssz + r0 + 8) * Csz + c) =
            __floats2half2_rn(oacc[nt][2]*inv1, oacc[nt][3]*inv1);
    }
}

// ---------------------------------------------------------------------------
extern "C" void kernel_launch(void* const* d_in, const int* in_sizes, int n_in,
                              void* d_out, int out_size)
{
    const float* x    = (const float*)d_in[0];
    const int*   mask = (const int*)  d_in[1];
    const float* W[3]   = {(const float*)d_in[2],  (const float*)d_in[8],  (const float*)d_in[14]};
    const float* Bi[3]  = {(const float*)d_in[3],  (const float*)d_in[9],  (const float*)d_in[15]};
    const float* DW[3]  = {(const float*)d_in[4],  (const float*)d_in[10], (const float*)d_in[16]};
    const float* DWB[3] = {(const float*)d_in[5],  (const float*)d_in[11], (const float*)d_in[17]};
    const float* PW[3]  = {(const float*)d_in[6],  (const float*)d_in[12], (const float*)d_in[18]};
    const float* PWB[3] = {(const float*)d_in[7],  (const float*)d_in[13], (const float*)d_in[19]};
    const float* wo = (const float*)d_in[20];
    const float* bo = (const float*)d_in[21];
    float* out = (float*)d_out;

    float *gf;
    __half *gh, *go, *vb, *wh, *wl;
    cudaGetSymbolAddress((void**)&gf, g_f32);
    cudaGetSymbolAddress((void**)&gh, g_h);
    cudaGetSymbolAddress((void**)&go, g_o);
    cudaGetSymbolAddress((void**)&vb, g_vb);
    cudaGetSymbolAddress((void**)&wh, g_wh);
    cudaGetSymbolAddress((void**)&wl, g_wl);
    const size_t PL = (size_t)Msz * Csz;
    const size_t WL = (size_t)Csz * Csz;

    const int GEMM_SMEM = 2 * G_STG;            // 49152
    const int ATT_SMEM  = 16384 + 2*ATT_STG;    // 49664
    cudaFuncSetAttribute(gemm_f16_k<0>, cudaFuncAttributeMaxDynamicSharedMemorySize, GEMM_SMEM);
    cudaFuncSetAttribute(gemm_f16_k<1>, cudaFuncAttributeMaxDynamicSharedMemorySize, GEMM_SMEM);
    cudaFuncSetAttribute(attn2_k, cudaFuncAttributeMaxDynamicSharedMemorySize, ATT_SMEM);

    const dim3 ggemm1(Csz/128, Msz/128, 1);
    const dim3 ggemm3(Csz/128, Msz/128, 3);
    const dim3 gtr(Csz/32, Csz/32), btr(32, 8);

    // 1) x -> fp16 (gh0)
    cvt_f16_k<<<(Msz*Csz/4)/256, 256>>>(x, gh);

    // 2) weight prep for QKV
    for (int p = 0; p < 3; p++)
        split_trans_k<<<gtr, btr>>>(W[p], wh + p*WL, wl + p*WL, Csz, Csz);

    // 3) batched QKV GEMM: q/k/v = silu(x @ W + b) -> gf[z]
    gemm_f16_k<1><<<ggemm3, 256, GEMM_SMEM>>>(
        gh, wh, wl, Bi[0], Bi[1], Bi[2], gf,
        Msz, Csz, Csz, 0, WL, PL);

    // 4) fused depthwise conv -> fp16: gf[z] -> gh[z]
    dwconv_f16_k<<<dim3((Msz*Csz/4)/256, 3), 256>>>(
        gf, DW[0], DW[1], DW[2], DWB[0], DWB[1], DWB[2], gh);

    // 5) weight prep for pointwise (PW already [N,K])
    for (int p = 0; p < 3; p++)
        split_k<<<(Csz*Csz/4)/256, 256>>>(PW[p], wh + p*WL, wl + p*WL);

    // 6) batched pointwise GEMM -> gf[z]
    gemm_f16_k<0><<<ggemm3, 256, GEMM_SMEM>>>(
        gh, wh, wl, PWB[0], PWB[1], PWB[2], gf,
        Msz, Csz, Csz, PL, WL, PL);

    // 7) l2norm q,k -> fp16; V -> fp16 transposed
    l2norm_f16_k<<<Msz, 256>>>(gf,      gh);
    l2norm_f16_k<<<Msz, 256>>>(gf + PL, gh + PL);
    vtrans_k<<<dim3(Ssz/32, Bsz*Hn*2), btr>>>(gf + 2*PL, vb);

    // 8) weight prep for out-proj
    split_trans_k<<<gtr, btr>>>(wo, wh, wl, Csz, Csz);

    // 9) attention -> plain fp16 output
    attn2_k<<<dim3(Ssz/128, Bsz*Hn), 256, ATT_SMEM>>>(
        gh, gh + PL, vb, mask, go);

    // 10) out = attn_out @ wo + bo
    gemm_f16_k<0><<<ggemm1, 256, GEMM_SMEM>>>(
        go, wh, wl, bo, bo, bo, out,
        Msz, Csz, Csz, 0, 0, 0);
}

// round 11
// speedup vs baseline: 5.6925x; 1.3178x over previous
#include <cuda_runtime.h>
#include <cuda_fp16.h>
#include <math.h>
#include <cstdint>

#define Bsz 4
#define Ssz 2048
#define Csz 1024
#define Hn  16
#define Dh  64
#define Msz (Bsz*Ssz)   // 8192

// Scratch
__device__ float  g_f32[3][(size_t)Msz*Csz];      // fp32 GEMM outputs
__device__ __half g_h[3][(size_t)Msz*Csz];        // fp16 activation planes
__device__ __half g_o[(size_t)Msz*Csz];           // fp16 attention output
__device__ __half g_vb[(size_t)Msz*Csz];          // V^T per (b,h): [d][s]
__device__ __half g_w[3][(size_t)Csz*Csz];        // fp16 weights [N,K]

// ---------------------------------------------------------------------------
// PTX helpers (arch-neutral: ldmatrix / mma.sync / cp.async)
// ---------------------------------------------------------------------------
__device__ __forceinline__ uint32_t smem_u32(const void* p) {
    uint32_t a;
    asm("{ .reg .u64 t; cvta.to.shared.u64 t, %1; cvt.u32.u64 %0, t; }" : "=r"(a) : "l"(p));
    return a;
}
__device__ __forceinline__ void cp16(uint32_t saddr, const void* g) {
    asm volatile("cp.async.cg.shared.global [%0], [%1], 16;" :: "r"(saddr), "l"(g));
}
__device__ __forceinline__ void cp4(uint32_t saddr, const void* g) {
    asm volatile("cp.async.ca.shared.global [%0], [%1], 4;" :: "r"(saddr), "l"(g));
}
#define CP_COMMIT() asm volatile("cp.async.commit_group;" ::: "memory")
#define CP_WAIT1()  asm volatile("cp.async.wait_group 1;" ::: "memory")
#define CP_WAIT0()  asm volatile("cp.async.wait_group 0;" ::: "memory")

#define LDSM4(r, addr)                                                          \
    asm volatile("ldmatrix.sync.aligned.m8n8.x4.shared.b16 {%0,%1,%2,%3}, [%4];" \
        : "=r"((r)[0]), "=r"((r)[1]), "=r"((r)[2]), "=r"((r)[3]) : "r"(addr))
#define LDSM2(r, addr)                                                          \
    asm volatile("ldmatrix.sync.aligned.m8n8.x2.shared.b16 {%0,%1}, [%2];"      \
        : "=r"((r)[0]), "=r"((r)[1]) : "r"(addr))

#define MMA16816(d, a, b)                                                       \
    asm volatile("mma.sync.aligned.m16n8k16.row.col.f32.f16.f16.f32 "           \
        "{%0,%1,%2,%3}, {%4,%5,%6,%7}, {%8,%9}, {%0,%1,%2,%3};"                 \
        : "+f"((d)[0]), "+f"((d)[1]), "+f"((d)[2]), "+f"((d)[3])                \
        : "r"((a)[0]), "r"((a)[1]), "r"((a)[2]), "r"((a)[3]),                   \
          "r"((b)[0]), "r"((b)[1]))

__device__ __forceinline__ uint32_t pack_f16(float lo, float hi) {
    uint32_t r;
    asm("cvt.rn.f16x2.f32 %0, %1, %2;" : "=r"(r) : "f"(hi), "f"(lo));
    return r;
}

// Swizzled smem offset for a [rows x 32] f16 tile (64B rows): granule g 0..3
__device__ __forceinline__ uint32_t tswz(int r, int g) {
    return (uint32_t)(r * 64 + ((g ^ ((r >> 1) & 3)) & 3) * 16);
}
// Swizzled offset for 128B rows (64 f16): granule g 0..7
__device__ __forceinline__ uint32_t tswz128(int r, int g) {
    return (uint32_t)(r * 128 + ((g ^ (r & 7)) & 7) * 16);
}

// ---------------------------------------------------------------------------
// Convert fp32 -> fp16 (plain)
// ---------------------------------------------------------------------------
__global__ void cvt_f16_k(const float* __restrict__ in, __half* __restrict__ out)
{
    const size_t i4 = (size_t)blockIdx.x * blockDim.x + threadIdx.x;
    float4 v = *(const float4*)(in + i4 * 4);
    *(__half2*)(out + i4*4)     = __floats2half2_rn(v.x, v.y);
    *(__half2*)(out + i4*4 + 2) = __floats2half2_rn(v.z, v.w);
}

// ---------------------------------------------------------------------------
// Transpose+convert: W[K,N] fp32 -> [N,K] fp16.
// ---------------------------------------------------------------------------
__global__ void cvt_trans_k(const float* __restrict__ W, __half* __restrict__ o,
                            int K, int N)
{
    __shared__ float t[32][33];
    const int k0 = blockIdx.y * 32, n0 = blockIdx.x * 32;
    const int tx = threadIdx.x, ty = threadIdx.y;
#pragma unroll
    for (int r = 0; r < 4; r++)
        t[ty + r*8][tx] = W[(size_t)(k0 + ty + r*8) * N + n0 + tx];
    __syncthreads();
#pragma unroll
    for (int r = 0; r < 4; r++) {
        const int n = n0 + ty + r*8, k = k0 + tx;
        o[(size_t)n * K + k] = __float2half_rn(t[tx][ty + r*8]);
    }
}

// ---------------------------------------------------------------------------
// V transpose to fp16: in [B,S,C] fp32 -> vt[(bh*64 + d)*Ssz + s]
// ---------------------------------------------------------------------------
__global__ void vtrans_k(const float* __restrict__ in, __half* __restrict__ vt)
{
    __shared__ float t[32][33];
    const int z = blockIdx.y;
    const int dblk = z & 1, bh = z >> 1;
    const int b = bh >> 4, h = bh & 15;
    const int s0 = blockIdx.x * 32;
    const int tx = threadIdx.x, ty = threadIdx.y;
#pragma unroll
    for (int r = 0; r < 4; r++)
        t[ty + r*8][tx] = in[(size_t)(b*Ssz + s0 + ty + r*8) * Csz + h*Dh + dblk*32 + tx];
    __syncthreads();
#pragma unroll
    for (int r = 0; r < 4; r++) {
        const int d = dblk*32 + ty + r*8;
        vt[((size_t)bh * Dh + d) * Ssz + s0 + tx] = __float2half_rn(t[tx][ty + r*8]);
    }
}

// ---------------------------------------------------------------------------
// Plain fp16 GEMM on mma.sync, batched over blockIdx.z.
// C[M,N] = act(A @ B^T + bias); A fp16 [M,K], B fp16 [N,K].
// 128x128 tile, BK=32, 256 threads, 2-stage cp.async pipeline.
// Stage layout (16KB): A | B @ 8KB each.
// ---------------------------------------------------------------------------
#define G_STG 16384
__device__ __forceinline__ void stage_load(
    const __half* __restrict__ A, const __half* __restrict__ B,
    int K, int m0, int n0, int k0, uint32_t sb)
{
    const int t = threadIdx.x;
    const int r = t >> 1;
    const int g0 = (t & 1) * 2;
    const size_t arow = (size_t)(m0 + r) * K + k0;
    const size_t brow = (size_t)(n0 + r) * K + k0;
#pragma unroll
    for (int gg = 0; gg < 2; gg++) {
        const int g = g0 + gg;
        const uint32_t so = tswz(r, g);
        cp16(sb + so,        A + arow + g*8);
        cp16(sb + 8192 + so, B + brow + g*8);
    }
}

template<int ACT>
__global__ __launch_bounds__(256, 1) void gemm_f16_k(
    const __half* __restrict__ A_, const __half* __restrict__ B_,
    const float* __restrict__ bias0, const float* __restrict__ bias1,
    const float* __restrict__ bias2,
    float* __restrict__ C_,
    int M, int N, int K, size_t strideA, size_t strideB, size_t strideC)
{
    extern __shared__ char sm_[];
    const uint32_t sbase = smem_u32(sm_);
    const int tid  = threadIdx.x;
    const int lane = tid & 31;
    const int warp = tid >> 5;
    const int wm = warp >> 2;
    const int wn = warp & 3;
    const int m0 = blockIdx.y * 128, n0 = blockIdx.x * 128;
    const int z  = blockIdx.z;

    const __half* A = A_ + (size_t)z * strideA;
    const __half* B = B_ + (size_t)z * strideB;
    const float* bias = (z == 0) ? bias0 : ((z == 1) ? bias1 : bias2);
    float* C = C_ + (size_t)z * strideC;

    float acc[4][4][4];
#pragma unroll
    for (int i = 0; i < 4; i++)
#pragma unroll
        for (int j = 0; j < 4; j++)
#pragma unroll
            for (int c = 0; c < 4; c++) acc[i][j][c] = 0.f;

    const int NIT = K >> 5;

    stage_load(A, B, K, m0, n0, 0, sbase);
    CP_COMMIT();

    for (int it = 0; it < NIT; it++) {
        if (it + 1 < NIT) {
            stage_load(A, B, K, m0, n0, (it+1) << 5,
                       sbase + ((it+1) & 1) * G_STG);
            CP_COMMIT();
            CP_WAIT1();
        } else {
            CP_WAIT0();
        }
        __syncthreads();

        const uint32_t sb = sbase + (it & 1) * G_STG;
        const int lr  = lane & 15;
        const int hf  = lane >> 4;
        const int lnb = lane & 7;
        const int hfb = (lane >> 3) & 1;

#pragma unroll
        for (int kk = 0; kk < 2; kk++) {
            uint32_t ah[4][4], bfr[4][2];
#pragma unroll
            for (int mt = 0; mt < 4; mt++) {
                const int r = wm*64 + mt*16 + lr;
                LDSM4(ah[mt], sb + tswz(r, kk*2 + hf));
            }
#pragma unroll
            for (int nt = 0; nt < 4; nt++) {
                const int rn = wn*32 + nt*8 + lnb;
                LDSM2(bfr[nt], sb + 8192 + tswz(rn, kk*2 + hfb));
            }
#pragma unroll
            for (int mt = 0; mt < 4; mt++)
#pragma unroll
                for (int nt = 0; nt < 4; nt++)
                    MMA16816(acc[mt][nt], ah[mt], bfr[nt]);
        }
        __syncthreads();
    }

    const int gid = lane >> 2;
    const int tg  = lane & 3;
#pragma unroll
    for (int mt = 0; mt < 4; mt++) {
#pragma unroll
        for (int nt = 0; nt < 4; nt++) {
            const int ncol = n0 + wn*32 + nt*8 + tg*2;
            const float b0 = __ldg(&bias[ncol]);
            const float b1 = __ldg(&bias[ncol + 1]);
#pragma unroll
            for (int h = 0; h < 2; h++) {
                const int row = m0 + wm*64 + mt*16 + gid + h*8;
                float v0 = acc[mt][nt][h*2 + 0] + b0;
                float v1 = acc[mt][nt][h*2 + 1] + b1;
                if (ACT) {
                    v0 = v0 / (1.f + __expf(-v0));
                    v1 = v1 / (1.f + __expf(-v1));
                }
                float2 o = make_float2(v0, v1);
                *(float2*)(C + (size_t)row * N + ncol) = o;
            }
        }
    }
}

// ---------------------------------------------------------------------------
// Fused depthwise conv k=3 + convert to fp16. Batched over z.
// ---------------------------------------------------------------------------
__global__ void dwconv_f16_k(
    const float* __restrict__ in_,
    const float* __restrict__ dw0, const float* __restrict__ dw1, const float* __restrict__ dw2,
    const float* __restrict__ db0, const float* __restrict__ db1, const float* __restrict__ db2,
    __half* __restrict__ out_)
{
    const int z = blockIdx.y;
    const float* in = in_ + (size_t)z * Msz * Csz;
    const float* dw  = (z == 0) ? dw0 : ((z == 1) ? dw1 : dw2);
    const float* dwb = (z == 0) ? db0 : ((z == 1) ? db1 : db2);
    __half* out = out_ + (size_t)z * Msz * Csz;

    const int idx = blockIdx.x * blockDim.x + threadIdx.x;
    const int c4 = (idx & (Csz/4 - 1)) * 4;
    const int m  = idx >> 8;
    const int s  = m & (Ssz - 1);

    float4 x0 = make_float4(0,0,0,0), x2 = make_float4(0,0,0,0);
    if (s > 0)        x0 = *(const float4*)(in + (size_t)(m-1)*Csz + c4);
    const float4 x1 =      *(const float4*)(in + (size_t)m*Csz + c4);
    if (s < Ssz - 1)  x2 = *(const float4*)(in + (size_t)(m+1)*Csz + c4);

    const float* p0 = &x0.x; const float* p1 = &x1.x; const float* p2 = &x2.x;
    float v[4];
#pragma unroll
    for (int t = 0; t < 4; t++) {
        const int c = c4 + t;
        v[t] = dwb[c] + dw[c*3+0]*p0[t] + dw[c*3+1]*p1[t] + dw[c*3+2]*p2[t];
    }
    *(__half2*)(out + (size_t)m*Csz + c4)     = __floats2half2_rn(v[0], v[1]);
    *(__half2*)(out + (size_t)m*Csz + c4 + 2) = __floats2half2_rn(v[2], v[3]);
}

// ---------------------------------------------------------------------------
// L2 normalize over C=1024, output fp16.
// ---------------------------------------------------------------------------
__global__ void l2norm_f16_k(const float* __restrict__ src, __half* __restrict__ dst)
{
    __shared__ float red[8];
    const float* p = src + (size_t)blockIdx.x * Csz;
    float4 v = *(const float4*)(p + threadIdx.x*4);
    float ss = v.x*v.x + v.y*v.y + v.z*v.z + v.w*v.w;
#pragma unroll
    for (int off = 16; off; off >>= 1) ss += __shfl_xor_sync(0xffffffffu, ss, off);
    if ((threadIdx.x & 31) == 0) red[threadIdx.x >> 5] = ss;
    __syncthreads();
    if (threadIdx.x == 0) {
        float t = 0.f;
#pragma unroll
        for (int i = 0; i < 8; i++) t += red[i];
        red[0] = t;
    }
    __syncthreads();
    const float inv = 1.0f / fmaxf(sqrtf(red[0]), 1e-12f);
    __half* d = dst + (size_t)blockIdx.x * Csz + threadIdx.x*4;
    *(__half2*)(d)     = __floats2half2_rn(v.x*inv, v.y*inv);
    *(__half2*)(d + 2) = __floats2half2_rn(v.z*inv, v.w*inv);
}

// ---------------------------------------------------------------------------
// Flash attention on mma.sync (fp16 in, fp32 accum). Output plain fp16.
// Block: 128 queries x (b,h). 8 warps. K/V chunks of 64, double-buffered.
// Stage = K(8KB) + V^T(8KB) + mask(256B) = 16640B.
// ---------------------------------------------------------------------------
#define ATT_STG 16640
__device__ __forceinline__ void attn_stage(
    const __half* __restrict__ kb, const __half* __restrict__ vt,
    const int* __restrict__ mask, size_t qkbase, size_t vbase, int b,
    int chunk, uint32_t st)
{
    const int tid = threadIdx.x;
#pragma unroll
    for (int i = 0; i < 2; i++) {
        const int idx = tid + i*256;
        const int r = idx >> 3, g = idx & 7;
        const uint32_t so = tswz128(r, g);
        cp16(st + so,        kb + qkbase + (size_t)(chunk*64 + r) * Csz + g*8);
        cp16(st + 8192 + so, vt + vbase + (size_t)r * Ssz + chunk*64 + g*8);
    }
    if (tid < 64)
        cp4(st + 16384 + tid*4, mask + (size_t)b * Ssz + chunk*64 + tid);
}

__global__ __launch_bounds__(256, 1) void attn2_k(
    const __half* __restrict__ qb, const __half* __restrict__ kb,
    const __half* __restrict__ vt, const int* __restrict__ mask,
    __half* __restrict__ og)
{
    extern __shared__ char sm_[];
    const uint32_t sbase = smem_u32(sm_);
    const int tid = threadIdx.x, lane = tid & 31, warp = tid >> 5;
    const int q0 = blockIdx.x * 128;
    const int bh = blockIdx.y;
    const int b = bh >> 4, h = bh & 15;

    const size_t qkbase = ((size_t)b * Ssz) * Csz + h * Dh;
    const size_t vbase  = (size_t)bh * Dh * Ssz;

    // Q -> smem (128 rows x 128B)
#pragma unroll
    for (int i = 0; i < 4; i++) {
        const int idx = tid + i*256;
        const int r = idx >> 3, g = idx & 7;
        cp16(sbase + tswz128(r, g), qb + qkbase + (size_t)(q0 + r) * Csz + g*8);
    }
    CP_COMMIT();

    const uint32_t kvb = sbase + 16384;
    attn_stage(kb, vt, mask, qkbase, vbase, b, 0, kvb);
    CP_COMMIT();

    float oacc[8][4];
#pragma unroll
    for (int nt = 0; nt < 8; nt++)
#pragma unroll
        for (int c = 0; c < 4; c++) oacc[nt][c] = 0.f;
    float m0 = -1e30f, m1 = -1e30f, l0 = 0.f, l1 = 0.f;
    uint32_t aq[4][4];

    const int cb = (lane & 3) * 2;

    for (int it = 0; it < Ssz/64; it++) {
        if (it + 1 < Ssz/64) {
            attn_stage(kb, vt, mask, qkbase, vbase, b, it+1, kvb + ((it+1)&1)*ATT_STG);
            CP_COMMIT();
            CP_WAIT1();
        } else {
            CP_WAIT0();
        }
        __syncthreads();

        if (it == 0) {
#pragma unroll
            for (int ks = 0; ks < 4; ks++) {
                const int r = warp*16 + (lane & 15);
                const int g = ks*2 + (lane >> 4);
                LDSM4(aq[ks], sbase + tswz128(r, g));
            }
        }

        const uint32_t st = kvb + (it & 1) * ATT_STG;
        const int* Ms = (const int*)(sm_ + 16384 + (it & 1) * ATT_STG + 16384);

        // S = Q K^T
        float sacc[8][4];
#pragma unroll
        for (int nt = 0; nt < 8; nt++)
#pragma unroll
            for (int c = 0; c < 4; c++) sacc[nt][c] = 0.f;

#pragma unroll
        for (int ks = 0; ks < 4; ks++) {
#pragma unroll
            for (int nt = 0; nt < 8; nt++) {
                uint32_t kf[2];
                const int r = nt*8 + (lane & 7);
                const int g = ks*2 + ((lane >> 3) & 1);
                LDSM2(kf, st + tswz128(r, g));
                MMA16816(sacc[nt], aq[ks], kf);
            }
        }

        // scale + mask + online softmax
        float mx0 = -1e30f, mx1 = -1e30f;
#pragma unroll
        for (int nt = 0; nt < 8; nt++) {
            const int c = nt*8 + cb;
            const bool k0m = Ms[c] != 0, k1m = Ms[c+1] != 0;
            sacc[nt][0] = k0m ? sacc[nt][0]*0.125f : -1e30f;
            sacc[nt][1] = k1m ? sacc[nt][1]*0.125f : -1e30f;
            sacc[nt][2] = k0m ? sacc[nt][2]*0.125f : -1e30f;
            sacc[nt][3] = k1m ? sacc[nt][3]*0.125f : -1e30f;
            mx0 = fmaxf(mx0, fmaxf(sacc[nt][0], sacc[nt][1]));
            mx1 = fmaxf(mx1, fmaxf(sacc[nt][2], sacc[nt][3]));
        }
        mx0 = fmaxf(mx0, __shfl_xor_sync(0xffffffffu, mx0, 1));
        mx0 = fmaxf(mx0, __shfl_xor_sync(0xffffffffu, mx0, 2));
        mx1 = fmaxf(mx1, __shfl_xor_sync(0xffffffffu, mx1, 1));
        mx1 = fmaxf(mx1, __shfl_xor_sync(0xffffffffu, mx1, 2));
        const float mn0 = fmaxf(m0, mx0), mn1 = fmaxf(m1, mx1);
        const float c0 = __expf(m0 - mn0), c1 = __expf(m1 - mn1);
        m0 = mn0; m1 = mn1;
        float rs0 = 0.f, rs1 = 0.f;
#pragma unroll
        for (int nt = 0; nt < 8; nt++) {
            sacc[nt][0] = __expf(sacc[nt][0] - mn0);
            sacc[nt][1] = __expf(sacc[nt][1] - mn0);
            sacc[nt][2] = __expf(sacc[nt][2] - mn1);
            sacc[nt][3] = __expf(sacc[nt][3] - mn1);
            rs0 += sacc[nt][0] + sacc[nt][1];
            rs1 += sacc[nt][2] + sacc[nt][3];
        }
        rs0 += __shfl_xor_sync(0xffffffffu, rs0, 1);
        rs0 += __shfl_xor_sync(0xffffffffu, rs0, 2);
        rs1 += __shfl_xor_sync(0xffffffffu, rs1, 1);
        rs1 += __shfl_xor_sync(0xffffffffu, rs1, 2);
        l0 = l0*c0 + rs0;
        l1 = l1*c1 + rs1;
#pragma unroll
        for (int nt = 0; nt < 8; nt++) {
            oacc[nt][0] *= c0; oacc[nt][1] *= c0;
            oacc[nt][2] *= c1; oacc[nt][3] *= c1;
        }

        // O += P V
#pragma unroll
        for (int ks = 0; ks < 4; ks++) {
            uint32_t pa[4];
            pa[0] = pack_f16(sacc[2*ks][0],   sacc[2*ks][1]);
            pa[1] = pack_f16(sacc[2*ks][2],   sacc[2*ks][3]);
            pa[2] = pack_f16(sacc[2*ks+1][0], sacc[2*ks+1][1]);
            pa[3] = pack_f16(sacc[2*ks+1][2], sacc[2*ks+1][3]);
#pragma unroll
            for (int nt = 0; nt < 8; nt++) {
                uint32_t vf[2];
                const int r = nt*8 + (lane & 7);
                const int g = ks*2 + ((lane >> 3) & 1);
                LDSM2(vf, st + 8192 + tswz128(r, g));
                MMA16816(oacc[nt], pa, vf);
            }
        }
        __syncthreads();
    }

    // Epilogue: normalize and emit plain fp16
    const float inv0 = 1.f / l0, inv1 = 1.f / l1;
    const int r0 = q0 + warp*16 + (lane >> 2);
#pragma unroll
    for (int nt = 0; nt < 8; nt++) {
        const int c = h*Dh + nt*8 + cb;
        *(__half2*)(og + ((size_t)b*Ssz + r0) * Csz + c) =
            __floats2half2_rn(oacc[nt][0]*inv0, oacc[nt][1]*inv0);
        *(__half2*)(og + ((size_t)b*Ssz + r0 + 8) * Csz + c) =
            __floats2half2_rn(oacc[nt][2]*inv1, oacc[nt][3]*inv1);
    }
}

// ---------------------------------------------------------------------------
extern "C" void kernel_launch(void* const* d_in, const int* in_sizes, int n_in,
                              void* d_out, int out_size)
{
    const float* x    = (const float*)d_in[0];
    const int*   mask = (const int*)  d_in[1];
    const float* W[3]   = {(const float*)d_in[2],  (const float*)d_in[8],  (const float*)d_in[14]};
    const float* Bi[3]  = {(const float*)d_in[3],  (const float*)d_in[9],  (const float*)d_in[15]};
    const float* DW[3]  = {(const float*)d_in[4],  (const float*)d_in[10], (const float*)d_in[16]};
    const float* DWB[3] = {(const float*)d_in[5],  (const float*)d_in[11], (const float*)d_in[17]};
    const float* PW[3]  = {(const float*)d_in[6],  (const float*)d_in[12], (const float*)d_in[18]};
    const float* PWB[3] = {(const float*)d_in[7],  (const float*)d_in[13], (const float*)d_in[19]};
    const float* wo = (const float*)d_in[20];
    const float* bo = (const float*)d_in[21];
    float* out = (float*)d_out;

    float *gf;
    __half *gh, *go, *vb, *gw;
    cudaGetSymbolAddress((void**)&gf, g_f32);
    cudaGetSymbolAddress((void**)&gh, g_h);
    cudaGetSymbolAddress((void**)&go, g_o);
    cudaGetSymbolAddress((void**)&vb, g_vb);
    cudaGetSymbolAddress((void**)&gw, g_w);
    const size_t PL = (size_t)Msz * Csz;
    const size_t WL = (size_t)Csz * Csz;

    const int GEMM_SMEM = 2 * G_STG;            // 32768
    const int ATT_SMEM  = 16384 + 2*ATT_STG;    // 49664
    cudaFuncSetAttribute(gemm_f16_k<0>, cudaFuncAttributeMaxDynamicSharedMemorySize, GEMM_SMEM);
    cudaFuncSetAttribute(gemm_f16_k<1>, cudaFuncAttributeMaxDynamicSharedMemorySize, GEMM_SMEM);
    cudaFuncSetAttribute(attn2_k, cudaFuncAttributeMaxDynamicSharedMemorySize, ATT_SMEM);

    const dim3 ggemm1(Csz/128, Msz/128, 1);
    const dim3 ggemm3(Csz/128, Msz/128, 3);
    const dim3 gtr(Csz/32, Csz/32), btr(32, 8);

    // 1) x -> fp16 (gh0)
    cvt_f16_k<<<(Msz*Csz/4)/256, 256>>>(x, gh);

    // 2) weight prep for QKV (transpose to [N,K] fp16)
    for (int p = 0; p < 3; p++)
        cvt_trans_k<<<gtr, btr>>>(W[p], gw + p*WL, Csz, Csz);

    // 3) batched QKV GEMM: q/k/v = silu(x @ W + b) -> gf[z]
    gemm_f16_k<1><<<ggemm3, 256, GEMM_SMEM>>>(
        gh, gw, Bi[0], Bi[1], Bi[2], gf,
        Msz, Csz, Csz, 0, WL, PL);

    // 4) fused depthwise conv -> fp16: gf[z] -> gh[z]
    dwconv_f16_k<<<dim3((Msz*Csz/4)/256, 3), 256>>>(
        gf, DW[0], DW[1], DW[2], DWB[0], DWB[1], DWB[2], gh);

    // 5) weight prep for pointwise (PW already [N,K], plain convert)
    cvt_f16_k<<<(Csz*Csz/4)/256, 256>>>(PW[0], gw);
    cvt_f16_k<<<(Csz*Csz/4)/256, 256>>>(PW[1], gw + WL);
    cvt_f16_k<<<(Csz*Csz/4)/256, 256>>>(PW[2], gw + 2*WL);

    // 6) batched pointwise GEMM -> gf[z]
    gemm_f16_k<0><<<ggemm3, 256, GEMM_SMEM>>>(
        gh, gw, PWB[0], PWB[1], PWB[2], gf,
        Msz, Csz, Csz, PL, WL, PL);

    // 7) l2norm q,k -> fp16; V -> fp16 transposed
    l2norm_f16_k<<<Msz, 256>>>(gf,      gh);
    l2norm_f16_k<<<Msz, 256>>>(gf + PL, gh + PL);
    vtrans_k<<<dim3(Ssz/32, Bsz*Hn*2), btr>>>(gf + 2*PL, vb);

    // 8) weight prep for out-proj
    cvt_trans_k<<<gtr, btr>>>(wo, gw, Csz, Csz);

    // 9) attention -> plain fp16 output
    attn2_k<<<dim3(Ssz/128, Bsz*Hn), 256, ATT_SMEM>>>(
        gh, gh + PL, vb, mask, go);

    // 10) out = attn_out @ wo + bo
    gemm_f16_k<0><<<ggemm1, 256, GEMM_SMEM>>>(
        go, gw, bo, bo, bo, out,
        Msz, Csz, Csz, 0, 0, 0);
}